// round 2
// baseline (speedup 1.0000x reference)
#include <cuda_runtime.h>
#include <math.h>
#include <stdint.h>

#define NN 100000
#define EE 1600000
#define BB 64
#define LN_EPS 1e-5f

// ---------------- scratch (static __device__ — no allocations allowed) ----------------
static __device__ int    g_deg[NN];
static __device__ int    g_rowstart[NN + 1];
static __device__ int    g_wptr[NN];
static __device__ float  g_dis[NN];
static __device__ float  g_selfw[NN];
static __device__ float4 g_edge[EE];    // {src_as_float, w, ea0, ea1}
static __device__ float2 g_esw[EE];     // {src_as_float, w}  (slim record for APPNP)
static __device__ float  g_t0[NN * 64];
static __device__ float  g_hA[NN * 128];
static __device__ float  g_hB[NN * 128];
static __device__ float  g_x0[NN * 128];
static __device__ float  g_gate[NN];
static __device__ float  g_bmax[BB];
static __device__ float  g_bsum[BB];
static __device__ int    g_part[64];
static __device__ int    g_is64e, g_is64b;

// ---------------- helpers ----------------
__device__ __forceinline__ int ldidx(const void* p, int is64, long long i) {
    if (is64) return (int)((const long long*)p)[i];
    return ((const int*)p)[i];
}

__device__ __forceinline__ float gelu(float x) {
    return 0.5f * x * (1.0f + erff(x * 0.70710678118654752440f));
}

__device__ __forceinline__ void atomicMaxF(float* a, float v) {
    int* ai = (int*)a;
    int old = *ai;
    while (__int_as_float(old) < v) {
        int assumed = old;
        old = atomicCAS(ai, assumed, __float_as_int(v));
        if (old == assumed) break;
    }
}

// ---------------- dtype detection ----------------
// Distinguish int32 vs int64 by OR-ing odd 32-bit words in the TAIL region of each
// buffer (batch is sorted ascending — the head is all zeros!). Under int64 all odd
// words are zero high-halves; under int32 they are real (nonzero) values.
__global__ void k_detect(const unsigned* ei, const unsigned* bt) {
    __shared__ unsigned s1[256], s2[256];
    int t = threadIdx.x;
    unsigned o1 = 0, o2 = 0;
    for (int i = t; i < 2048; i += 256) {
        o1 |= ei[(long long)2 * EE - 4096 + 2 * i + 1];
        o2 |= bt[NN - 4096 + 2 * i + 1];
    }
    s1[t] = o1; s2[t] = o2;
    __syncthreads();
    for (int o = 128; o; o >>= 1) {
        if (t < o) { s1[t] |= s1[t + o]; s2[t] |= s2[t + o]; }
        __syncthreads();
    }
    if (t == 0) { g_is64e = (s1[0] == 0); g_is64b = (s2[0] == 0); }
}

// ---------------- init ----------------
__global__ void k_init(float* outg) {
    int i = blockIdx.x * blockDim.x + threadIdx.x;
    if (i < NN) g_deg[i] = 0;
    if (i < BB) { g_bmax[i] = __int_as_float(0xff800000); g_bsum[i] = 0.f; }
    if (i < BB * 128) outg[i] = 0.f;
    if (i == 0) g_rowstart[NN] = EE;
}

// ---------------- degree histogram ----------------
__global__ void k_hist(const void* ei) {
    int e = blockIdx.x * blockDim.x + threadIdx.x;
    if (e >= EE) return;
    int d = ldidx(ei, g_is64e, (long long)EE + e);
    atomicAdd(&g_deg[d], 1);
}

// ---------------- 3-phase exclusive scan of degrees ----------------
#define SCHUNK 8192
#define SNB 13  // ceil(100000/8192)

__global__ void k_scan_sum() {
    __shared__ int sh[8];
    int b = blockIdx.x, t = threadIdx.x;
    int base = b * SCHUNK, s = 0;
    for (int i = t; i < SCHUNK; i += 256) {
        int idx = base + i;
        if (idx < NN) s += g_deg[idx];
    }
    for (int o = 16; o; o >>= 1) s += __shfl_xor_sync(~0u, s, o);
    if ((t & 31) == 0) sh[t >> 5] = s;
    __syncthreads();
    if (t == 0) {
        int v = 0;
        for (int i = 0; i < 8; i++) v += sh[i];
        g_part[b] = v;
    }
}

__global__ void k_scan_part() {
    if (threadIdx.x == 0) {
        int r = 0;
        for (int i = 0; i < SNB; i++) { int v = g_part[i]; g_part[i] = r; r += v; }
    }
}

__global__ void k_scan_write() {
    __shared__ int sh[1024];
    int b = blockIdx.x, t = threadIdx.x;
    int base = b * SCHUNK + t * 8;
    int loc[8];
    int s = 0;
#pragma unroll
    for (int j = 0; j < 8; j++) {
        int idx = base + j;
        int v = (idx < NN) ? g_deg[idx] : 0;
        loc[j] = s; s += v;
    }
    sh[t] = s;
    __syncthreads();
    for (int off = 1; off < 1024; off <<= 1) {
        int v = (t >= off) ? sh[t - off] : 0;
        __syncthreads();
        sh[t] += v;
        __syncthreads();
    }
    int off0 = g_part[b] + sh[t] - s;
#pragma unroll
    for (int j = 0; j < 8; j++) {
        int idx = base + j;
        if (idx < NN) {
            int rs = off0 + loc[j];
            g_rowstart[idx] = rs;
            g_wptr[idx] = rs;
            int d = g_deg[idx] + 1;
            g_dis[idx] = rsqrtf((float)d);
            g_selfw[idx] = 1.0f / (float)d;
        }
    }
}

// ---------------- CSR build ----------------
__global__ void k_build(const void* ei, const float* __restrict__ ea) {
    int e = blockIdx.x * blockDim.x + threadIdx.x;
    if (e >= EE) return;
    int is64 = g_is64e;
    int s = ldidx(ei, is64, e);
    int d = ldidx(ei, is64, (long long)EE + e);
    int pos = atomicAdd(&g_wptr[d], 1);
    float2 a = ((const float2*)ea)[e];
    float w = g_dis[s] * g_dis[d];
    g_edge[pos] = make_float4(__int_as_float(s), w, a.x, a.y);
    g_esw[pos] = make_float2(__int_as_float(s), w);
}

// ---------------- conv1 aggregation (64-dim, warp per dst) ----------------
__global__ void __launch_bounds__(256) k_conv1(const float* __restrict__ x,
                                               const float* __restrict__ We1,
                                               const float* __restrict__ be1) {
    int gt = blockIdx.x * blockDim.x + threadIdx.x;
    int row = gt >> 5;
    if (row >= NN) return;
    int lane = gt & 31, c = 2 * lane;
    float w0x = We1[c], w0y = We1[c + 1];
    float w1x = We1[64 + c], w1y = We1[64 + c + 1];
    float bx = be1[c], by = be1[c + 1];
    int beg = g_rowstart[row], end = g_rowstart[row + 1];
    float ax = 0.f, ay = 0.f;
    for (int p = beg; p < end; p++) {
        float4 r = g_edge[p];
        int s = __float_as_int(r.x);
        float2 xv = *(const float2*)(x + (size_t)s * 64 + c);
        ax += fmaxf(xv.x + r.z * w0x + r.w * w1x + bx, 0.f);
        ay += fmaxf(xv.y + r.z * w0y + r.w * w1y + by, 0.f);
    }
    float2 xd = *(const float2*)(x + (size_t)row * 64 + c);
    *(float2*)(g_t0 + (size_t)row * 64 + c) = make_float2(ax + xd.x, ay + xd.y);
}

// ---------------- conv2 aggregation (128-dim, warp per dst) ----------------
__global__ void __launch_bounds__(256) k_conv2(const float* __restrict__ hin,
                                               float* __restrict__ hout,
                                               const float* __restrict__ We2,
                                               const float* __restrict__ be2) {
    int gt = blockIdx.x * blockDim.x + threadIdx.x;
    int row = gt >> 5;
    if (row >= NN) return;
    int lane = gt & 31, c = 4 * lane;
    float4 w0 = *(const float4*)(We2 + c);
    float4 w1 = *(const float4*)(We2 + 128 + c);
    float4 bv = *(const float4*)(be2 + c);
    int beg = g_rowstart[row], end = g_rowstart[row + 1];
    float4 acc = make_float4(0.f, 0.f, 0.f, 0.f);
    for (int p = beg; p < end; p++) {
        float4 r = g_edge[p];
        int s = __float_as_int(r.x);
        float4 hv = *(const float4*)(hin + (size_t)s * 128 + c);
        acc.x += fmaxf(hv.x + r.z * w0.x + r.w * w1.x + bv.x, 0.f);
        acc.y += fmaxf(hv.y + r.z * w0.y + r.w * w1.y + bv.y, 0.f);
        acc.z += fmaxf(hv.z + r.z * w0.z + r.w * w1.z + bv.z, 0.f);
        acc.w += fmaxf(hv.w + r.z * w0.w + r.w * w1.w + bv.w, 0.f);
    }
    float4 hd = *(const float4*)(hin + (size_t)row * 128 + c);
    *(float4*)(hout + (size_t)row * 128 + c) =
        make_float4(hd.x + acc.x, hd.y + acc.y, hd.z + acc.z, hd.w + acc.w);
}

// ---------------- fused MLP(+optional GELU)+LayerNorm ----------------
// Both weight matrices in dynamic SMEM; each thread computes 2 nodes x 2 cols.
template <int K1, int GELU_OUT>
__global__ void __launch_bounds__(256, 1)
k_mlp(const float* __restrict__ in, float* __restrict__ out,
      const float* __restrict__ Wa, const float* __restrict__ ba,
      const float* __restrict__ Wb, const float* __restrict__ bb,
      const float* __restrict__ gamma, const float* __restrict__ beta) {
    extern __shared__ float sm[];
    float* sWa = sm;                     // K1*128
    float* sWb = sWa + K1 * 128;         // 128*128
    float* sx = sWb + 128 * 128;         // 8*K1
    float* su = sx + 8 * K1;             // 8*128
    float* sred = su + 8 * 128;          // 32

    int t = threadIdx.x;
    for (int i = t; i < K1 * 128; i += 256) sWa[i] = Wa[i];
    for (int i = t; i < 128 * 128; i += 256) sWb[i] = Wb[i];

    int pr = t >> 6;            // node pair 0..3  (nodes 2*pr, 2*pr+1)
    int j = t & 63;
    int c0 = 2 * j;
    int lane = t & 31;
    int wpn = (t >> 5) & 1;

    float ba0 = ba[c0], ba1 = ba[c0 + 1];
    float bb0 = bb[c0], bb1 = bb[c0 + 1];
    float gm0 = gamma[c0], gm1 = gamma[c0 + 1];
    float bt0 = beta[c0], bt1 = beta[c0 + 1];
    __syncthreads();

    int ntiles = (NN + 7) / 8;
    for (int tile = blockIdx.x; tile < ntiles; tile += gridDim.x) {
        int nbase = tile * 8;
        __syncthreads();
        for (int i = t; i < 8 * K1; i += 256) {
            int n = nbase + i / K1;
            sx[i] = (n < NN) ? in[(size_t)n * K1 + (i % K1)] : 0.f;
        }
        __syncthreads();

        const float* x0p = sx + (2 * pr) * K1;
        const float* x1p = x0p + K1;
        float a00 = ba0, a01 = ba1, a10 = ba0, a11 = ba1;
#pragma unroll 8
        for (int k = 0; k < K1; k++) {
            float2 w = *(const float2*)(sWa + k * 128 + c0);
            float xa = x0p[k], xb = x1p[k];
            a00 += xa * w.x; a01 += xa * w.y;
            a10 += xb * w.x; a11 += xb * w.y;
        }
        a00 = gelu(a00); a01 = gelu(a01); a10 = gelu(a10); a11 = gelu(a11);
        *(float2*)(su + (2 * pr) * 128 + c0) = make_float2(a00, a01);
        *(float2*)(su + (2 * pr + 1) * 128 + c0) = make_float2(a10, a11);
        __syncthreads();

        const float* u0p = su + (2 * pr) * 128;
        const float* u1p = u0p + 128;
        float y00 = bb0, y01 = bb1, y10 = bb0, y11 = bb1;
#pragma unroll 8
        for (int k = 0; k < 128; k++) {
            float2 w = *(const float2*)(sWb + k * 128 + c0);
            float ua = u0p[k], ub = u1p[k];
            y00 += ua * w.x; y01 += ua * w.y;
            y10 += ub * w.x; y11 += ub * w.y;
        }
        if (GELU_OUT) { y00 = gelu(y00); y01 = gelu(y01); y10 = gelu(y10); y11 = gelu(y11); }

        float s0 = y00 + y01, q0 = y00 * y00 + y01 * y01;
        float s1 = y10 + y11, q1 = y10 * y10 + y11 * y11;
        for (int o = 16; o; o >>= 1) {
            s0 += __shfl_xor_sync(~0u, s0, o); q0 += __shfl_xor_sync(~0u, q0, o);
            s1 += __shfl_xor_sync(~0u, s1, o); q1 += __shfl_xor_sync(~0u, q1, o);
        }
        if (lane == 0) {
            int base = pr * 8 + wpn * 4;
            sred[base + 0] = s0; sred[base + 1] = q0;
            sred[base + 2] = s1; sred[base + 3] = q1;
        }
        __syncthreads();
        float S0 = sred[pr * 8 + 0] + sred[pr * 8 + 4];
        float Q0 = sred[pr * 8 + 1] + sred[pr * 8 + 5];
        float S1 = sred[pr * 8 + 2] + sred[pr * 8 + 6];
        float Q1 = sred[pr * 8 + 3] + sred[pr * 8 + 7];
        float mu0 = S0 * (1.f / 128.f);
        float var0 = Q0 * (1.f / 128.f) - mu0 * mu0;
        float inv0 = rsqrtf(var0 + LN_EPS);
        float mu1 = S1 * (1.f / 128.f);
        float var1 = Q1 * (1.f / 128.f) - mu1 * mu1;
        float inv1 = rsqrtf(var1 + LN_EPS);
        int n0 = nbase + 2 * pr, n1 = n0 + 1;
        if (n0 < NN) {
            out[(size_t)n0 * 128 + c0]     = (y00 - mu0) * inv0 * gm0 + bt0;
            out[(size_t)n0 * 128 + c0 + 1] = (y01 - mu0) * inv0 * gm1 + bt1;
        }
        if (n1 < NN) {
            out[(size_t)n1 * 128 + c0]     = (y10 - mu1) * inv1 * gm0 + bt0;
            out[(size_t)n1 * 128 + c0 + 1] = (y11 - mu1) * inv1 * gm1 + bt1;
        }
    }
}

// ---------------- APPNP step (warp per dst row) ----------------
__global__ void __launch_bounds__(256) k_appnp(const float* __restrict__ cur,
                                               float* __restrict__ nxt) {
    int gt = blockIdx.x * blockDim.x + threadIdx.x;
    int row = gt >> 5;
    if (row >= NN) return;
    int lane = gt & 31, c = 4 * lane;
    int beg = g_rowstart[row], end = g_rowstart[row + 1];
    float4 acc = make_float4(0.f, 0.f, 0.f, 0.f);
    for (int p = beg; p < end; p++) {
        float2 r = g_esw[p];
        int s = __float_as_int(r.x);
        float4 hv = *(const float4*)(cur + (size_t)s * 128 + c);
        acc.x += r.y * hv.x; acc.y += r.y * hv.y;
        acc.z += r.y * hv.z; acc.w += r.y * hv.w;
    }
    float sw = g_selfw[row];
    float4 hd = *(const float4*)(cur + (size_t)row * 128 + c);
    float4 xv = *(const float4*)(g_x0 + (size_t)row * 128 + c);
    float4 o;
    o.x = 0.9f * (acc.x + sw * hd.x) + 0.1f * xv.x;
    o.y = 0.9f * (acc.y + sw * hd.y) + 0.1f * xv.y;
    o.z = 0.9f * (acc.z + sw * hd.z) + 0.1f * xv.z;
    o.w = 0.9f * (acc.w + sw * hd.w) + 0.1f * xv.w;
    *(float4*)(nxt + (size_t)row * 128 + c) = o;
}

// ---------------- gate MLP + segment max ----------------
__global__ void __launch_bounds__(256) k_gate(const float* __restrict__ h,
                                              const float* __restrict__ Wg1,
                                              const float* __restrict__ bg1,
                                              const float* __restrict__ Wg2,
                                              const float* __restrict__ bg2,
                                              const void* bt) {
    __shared__ float sW[128 * 64];
    __shared__ float sx[4 * 128];
    __shared__ float sred[8];
    __shared__ float sWg2[64];
    int t = threadIdx.x;
    for (int i = t; i < 128 * 64; i += 256) sW[i] = Wg1[i];
    if (t < 64) sWg2[t] = Wg2[t];
    int nd = t >> 6, j = t & 63, lane = t & 31, w2 = (t >> 5) & 1;
    float bj = bg1[j];
    float b2 = bg2[0];
    int is64 = g_is64b;
    __syncthreads();

    int ntiles = (NN + 3) / 4;
    for (int tile = blockIdx.x; tile < ntiles; tile += gridDim.x) {
        int nbase = tile * 4;
        __syncthreads();
        for (int i = t; i < 4 * 128; i += 256) {
            int n = nbase + (i >> 7);
            sx[i] = (n < NN) ? h[(size_t)n * 128 + (i & 127)] : 0.f;
        }
        __syncthreads();
        const float* xr = sx + nd * 128;
        float v = bj;
#pragma unroll 8
        for (int k = 0; k < 128; k++) v += xr[k] * sW[k * 64 + j];
        v = gelu(v) * sWg2[j];
        for (int o = 16; o; o >>= 1) v += __shfl_xor_sync(~0u, v, o);
        if (lane == 0) sred[nd * 2 + w2] = v;
        __syncthreads();
        if (j == 0) {
            int n = nbase + nd;
            if (n < NN) {
                float gate = sred[nd * 2] + sred[nd * 2 + 1] + b2;
                g_gate[n] = gate;
                int b = ldidx(bt, is64, n);
                atomicMaxF(&g_bmax[b], gate);
            }
        }
    }
}

// ---------------- softmax denom ----------------
__global__ void k_exp(const void* bt) {
    int i = blockIdx.x * blockDim.x + threadIdx.x;
    if (i >= NN) return;
    int b = ldidx(bt, g_is64b, i);
    float e = expf(g_gate[i] - g_bmax[b]);
    g_gate[i] = e;
    atomicAdd(&g_bsum[b], e);
}

// ---------------- weighted pooling ----------------
__global__ void k_gagg(const float* __restrict__ h, float* __restrict__ outg,
                       const void* bt) {
    int i = blockIdx.x * blockDim.x + threadIdx.x;
    if (i >= NN * 128) return;
    int node = i >> 7, c = i & 127;
    int b = ldidx(bt, g_is64b, node);
    float s = g_bsum[b];
    if (s > 0.f) {
        float a = g_gate[node] / s;
        atomicAdd(&outg[b * 128 + c], a * h[i]);
    }
}

// ---------------- launch ----------------
extern "C" void kernel_launch(void* const* d_in, const int* in_sizes, int n_in,
                              void* d_out, int out_size) {
    const float* x = (const float*)d_in[0];
    const void* ei = d_in[1];
    const void* bt = d_in[2];
    const float* ea = (const float*)d_in[3];
    const float* We1 = (const float*)d_in[4];  const float* be1 = (const float*)d_in[5];
    const float* W1a = (const float*)d_in[6];  const float* b1a = (const float*)d_in[7];
    const float* W1b = (const float*)d_in[8];  const float* b1b = (const float*)d_in[9];
    const float* g1  = (const float*)d_in[10]; const float* bn1 = (const float*)d_in[11];
    const float* We2 = (const float*)d_in[12]; const float* be2 = (const float*)d_in[13];
    const float* W2a = (const float*)d_in[14]; const float* b2a = (const float*)d_in[15];
    const float* W2b = (const float*)d_in[16]; const float* b2b = (const float*)d_in[17];
    const float* g2  = (const float*)d_in[18]; const float* bn2 = (const float*)d_in[19];
    const float* Wg1 = (const float*)d_in[20]; const float* bg1 = (const float*)d_in[21];
    const float* Wg2 = (const float*)d_in[22]; const float* bg2 = (const float*)d_in[23];

    float* outh = (float*)d_out;
    float* outg = outh + (size_t)NN * 128;

    float *pT0, *pA, *pB, *pX0;
    cudaGetSymbolAddress((void**)&pT0, g_t0);
    cudaGetSymbolAddress((void**)&pA, g_hA);
    cudaGetSymbolAddress((void**)&pB, g_hB);
    cudaGetSymbolAddress((void**)&pX0, g_x0);

    size_t sz1 = (size_t)(64 * 128 + 128 * 128 + 8 * 64 + 8 * 128 + 32) * sizeof(float);
    size_t sz2 = (size_t)(128 * 128 + 128 * 128 + 8 * 128 + 8 * 128 + 32) * sizeof(float);
    cudaFuncSetAttribute(k_mlp<64, 1>, cudaFuncAttributeMaxDynamicSharedMemorySize, (int)sz1);
    cudaFuncSetAttribute(k_mlp<128, 0>, cudaFuncAttributeMaxDynamicSharedMemorySize, (int)sz2);

    k_detect<<<1, 256>>>((const unsigned*)ei, (const unsigned*)bt);
    k_init<<<(NN + 255) / 256, 256>>>(outg);
    k_hist<<<(EE + 255) / 256, 256>>>(ei);
    k_scan_sum<<<SNB, 256>>>();
    k_scan_part<<<1, 32>>>();
    k_scan_write<<<SNB, 1024>>>();
    k_build<<<(EE + 255) / 256, 256>>>(ei, ea);

    k_conv1<<<(NN * 32 + 255) / 256, 256>>>(x, We1, be1);
    k_mlp<64, 1><<<296, 256, sz1>>>(pT0, pA, W1a, b1a, W1b, b1b, g1, bn1);
    k_conv2<<<(NN * 32 + 255) / 256, 256>>>(pA, pB, We2, be2);
    k_mlp<128, 0><<<296, 256, sz2>>>(pB, pX0, W2a, b2a, W2b, b2b, g2, bn2);

    const float* cur = pX0;
    for (int it = 0; it < 16; it++) {
        float* nxt = (it == 15) ? outh : ((it & 1) ? pB : pA);
        k_appnp<<<(NN * 32 + 255) / 256, 256>>>(cur, nxt);
        cur = nxt;
    }

    k_gate<<<296, 256>>>(outh, Wg1, bg1, Wg2, bg2, bt);
    k_exp<<<(NN + 255) / 256, 256>>>(bt);
    k_gagg<<<(NN * 128 + 255) / 256, 256>>>(outh, outg, bt);
}

// round 5
// speedup vs baseline: 1.2488x; 1.2488x over previous
#include <cuda_runtime.h>
#include <cuda_fp16.h>
#include <math.h>
#include <stdint.h>

#define NN 100000
#define EE 1600000
#define BB 64
#define LN_EPS 1e-5f

// ---------------- scratch (static __device__ — no allocations allowed) ----------------
static __device__ int    g_deg[NN];
static __device__ int    g_rowstart[NN + 1];
static __device__ int    g_wptr[NN];
static __device__ float  g_dis[NN];
static __device__ float  g_selfw[NN];
static __device__ float4 g_edge[EE];    // {src_as_float, w, ea0, ea1}
static __device__ float2 g_esw[EE];     // {src_as_float, w}  (slim record for APPNP)
static __device__ float  g_t0[NN * 64];
static __device__ float  g_hB[NN * 128];       // conv2 output (fp32, mlp2 input)
static __device__ __half g_x16[NN * 64];       // fp16 copy of x for conv1 gathers
static __device__ __half g_h16A[NN * 128];     // mlp1 out (fp16) / APPNP ping
static __device__ __half g_h16B[NN * 128];     // APPNP pong
static __device__ __half g_x0h[NN * 128];      // mlp2 out (fp16): APPNP x0 + initial cur
static __device__ float  g_gate[NN];
static __device__ float  g_bmax[BB];
static __device__ float  g_bsum[BB];
static __device__ int    g_part[64];
static __device__ int    g_is64e, g_is64b;

// ---------------- helpers ----------------
__device__ __forceinline__ int ldidx(const void* p, int is64, long long i) {
    if (is64) return (int)((const long long*)p)[i];
    return ((const int*)p)[i];
}

__device__ __forceinline__ float gelu(float x) {
    return 0.5f * x * (1.0f + erff(x * 0.70710678118654752440f));
}

__device__ __forceinline__ void atomicMaxF(float* a, float v) {
    int* ai = (int*)a;
    int old = *ai;
    while (__int_as_float(old) < v) {
        int assumed = old;
        old = atomicCAS(ai, assumed, __float_as_int(v));
        if (old == assumed) break;
    }
}

// load 4 consecutive halves as 2 float2 values (one 8B load)
__device__ __forceinline__ float4 ldh4(const __half* p) {
    float2 raw = *(const float2*)p;
    __half2 lo = *(__half2*)&raw.x;
    __half2 hi = *(__half2*)&raw.y;
    float2 a = __half22float2(lo), b = __half22float2(hi);
    return make_float4(a.x, a.y, b.x, b.y);
}

__device__ __forceinline__ void sth4(__half* p, float4 v) {
    __half2 lo = __float22half2_rn(make_float2(v.x, v.y));
    __half2 hi = __float22half2_rn(make_float2(v.z, v.w));
    float2 raw;
    *(__half2*)&raw.x = lo;
    *(__half2*)&raw.y = hi;
    *(float2*)p = raw;
}

// ---------------- dtype detection ----------------
__global__ void k_detect(const unsigned* ei, const unsigned* bt) {
    __shared__ unsigned s1[256], s2[256];
    int t = threadIdx.x;
    unsigned o1 = 0, o2 = 0;
    for (int i = t; i < 2048; i += 256) {
        o1 |= ei[(long long)2 * EE - 4096 + 2 * i + 1];
        o2 |= bt[NN - 4096 + 2 * i + 1];
    }
    s1[t] = o1; s2[t] = o2;
    __syncthreads();
    for (int o = 128; o; o >>= 1) {
        if (t < o) { s1[t] |= s1[t + o]; s2[t] |= s2[t + o]; }
        __syncthreads();
    }
    if (t == 0) { g_is64e = (s1[0] == 0); g_is64b = (s2[0] == 0); }
}

// ---------------- init + x->fp16 ----------------
__global__ void k_init(float* outg, const float* __restrict__ x) {
    int i = blockIdx.x * blockDim.x + threadIdx.x;
    if (i < NN) g_deg[i] = 0;
    if (i < BB) { g_bmax[i] = __int_as_float(0xff800000); g_bsum[i] = 0.f; }
    if (i < BB * 128) outg[i] = 0.f;
    if (i == 0) g_rowstart[NN] = EE;
    if (i < NN * 32) {  // convert x (NN*64 floats) as pairs
        float2 v = ((const float2*)x)[i];
        ((__half2*)g_x16)[i] = __float22half2_rn(v);
    }
}

// ---------------- degree histogram ----------------
__global__ void k_hist(const void* ei) {
    int e = blockIdx.x * blockDim.x + threadIdx.x;
    if (e >= EE) return;
    int d = ldidx(ei, g_is64e, (long long)EE + e);
    atomicAdd(&g_deg[d], 1);
}

// ---------------- 3-phase exclusive scan of degrees ----------------
#define SCHUNK 8192
#define SNB 13

__global__ void k_scan_sum() {
    __shared__ int sh[8];
    int b = blockIdx.x, t = threadIdx.x;
    int base = b * SCHUNK, s = 0;
    for (int i = t; i < SCHUNK; i += 256) {
        int idx = base + i;
        if (idx < NN) s += g_deg[idx];
    }
    for (int o = 16; o; o >>= 1) s += __shfl_xor_sync(~0u, s, o);
    if ((t & 31) == 0) sh[t >> 5] = s;
    __syncthreads();
    if (t == 0) {
        int v = 0;
        for (int i = 0; i < 8; i++) v += sh[i];
        g_part[b] = v;
    }
}

__global__ void k_scan_part() {
    if (threadIdx.x == 0) {
        int r = 0;
        for (int i = 0; i < SNB; i++) { int v = g_part[i]; g_part[i] = r; r += v; }
    }
}

__global__ void k_scan_write() {
    __shared__ int sh[1024];
    int b = blockIdx.x, t = threadIdx.x;
    int base = b * SCHUNK + t * 8;
    int loc[8];
    int s = 0;
#pragma unroll
    for (int j = 0; j < 8; j++) {
        int idx = base + j;
        int v = (idx < NN) ? g_deg[idx] : 0;
        loc[j] = s; s += v;
    }
    sh[t] = s;
    __syncthreads();
    for (int off = 1; off < 1024; off <<= 1) {
        int v = (t >= off) ? sh[t - off] : 0;
        __syncthreads();
        sh[t] += v;
        __syncthreads();
    }
    int off0 = g_part[b] + sh[t] - s;
#pragma unroll
    for (int j = 0; j < 8; j++) {
        int idx = base + j;
        if (idx < NN) {
            int rs = off0 + loc[j];
            g_rowstart[idx] = rs;
            g_wptr[idx] = rs;
            int d = g_deg[idx] + 1;
            g_dis[idx] = rsqrtf((float)d);
            g_selfw[idx] = 1.0f / (float)d;
        }
    }
}

// ---------------- CSR build ----------------
__global__ void k_build(const void* ei, const float* __restrict__ ea) {
    int e = blockIdx.x * blockDim.x + threadIdx.x;
    if (e >= EE) return;
    int is64 = g_is64e;
    int s = ldidx(ei, is64, e);
    int d = ldidx(ei, is64, (long long)EE + e);
    int pos = atomicAdd(&g_wptr[d], 1);
    float2 a = ((const float2*)ea)[e];
    float w = g_dis[s] * g_dis[d];
    g_edge[pos] = make_float4(__int_as_float(s), w, a.x, a.y);
    g_esw[pos] = make_float2(__int_as_float(s), w);
}

// ---------------- conv1 aggregation (64-dim, warp per dst, fp16 gathers) ----------------
__global__ void __launch_bounds__(256) k_conv1(const float* __restrict__ x,
                                               const float* __restrict__ We1,
                                               const float* __restrict__ be1) {
    int gt = blockIdx.x * blockDim.x + threadIdx.x;
    int row = gt >> 5;
    if (row >= NN) return;
    int lane = gt & 31, c = 2 * lane;
    float w0x = We1[c], w0y = We1[c + 1];
    float w1x = We1[64 + c], w1y = We1[64 + c + 1];
    float bx = be1[c], by = be1[c + 1];
    int beg = g_rowstart[row], end = g_rowstart[row + 1];
    float ax = 0.f, ay = 0.f;
    int p = beg;
    for (; p + 2 <= end; p += 2) {
        float4 r0 = g_edge[p];
        float4 r1 = g_edge[p + 1];
        int s0 = __float_as_int(r0.x), s1 = __float_as_int(r1.x);
        float2 xv0 = __half22float2(*(const __half2*)(g_x16 + (size_t)s0 * 64 + c));
        float2 xv1 = __half22float2(*(const __half2*)(g_x16 + (size_t)s1 * 64 + c));
        ax += fmaxf(xv0.x + r0.z * w0x + r0.w * w1x + bx, 0.f);
        ay += fmaxf(xv0.y + r0.z * w0y + r0.w * w1y + by, 0.f);
        ax += fmaxf(xv1.x + r1.z * w0x + r1.w * w1x + bx, 0.f);
        ay += fmaxf(xv1.y + r1.z * w0y + r1.w * w1y + by, 0.f);
    }
    if (p < end) {
        float4 r = g_edge[p];
        int s = __float_as_int(r.x);
        float2 xv = __half22float2(*(const __half2*)(g_x16 + (size_t)s * 64 + c));
        ax += fmaxf(xv.x + r.z * w0x + r.w * w1x + bx, 0.f);
        ay += fmaxf(xv.y + r.z * w0y + r.w * w1y + by, 0.f);
    }
    float2 xd = *(const float2*)(x + (size_t)row * 64 + c);
    *(float2*)(g_t0 + (size_t)row * 64 + c) = make_float2(ax + xd.x, ay + xd.y);
}

// ---------------- conv2 aggregation (128-dim, warp per dst, fp16 gathers) ----------------
__global__ void __launch_bounds__(256) k_conv2(const __half* __restrict__ hin,
                                               float* __restrict__ hout,
                                               const float* __restrict__ We2,
                                               const float* __restrict__ be2) {
    int gt = blockIdx.x * blockDim.x + threadIdx.x;
    int row = gt >> 5;
    if (row >= NN) return;
    int lane = gt & 31, c = 4 * lane;
    float4 w0 = *(const float4*)(We2 + c);
    float4 w1 = *(const float4*)(We2 + 128 + c);
    float4 bv = *(const float4*)(be2 + c);
    int beg = g_rowstart[row], end = g_rowstart[row + 1];
    float4 acc = make_float4(0.f, 0.f, 0.f, 0.f);
    int p = beg;
    for (; p + 2 <= end; p += 2) {
        float4 r0 = g_edge[p];
        float4 r1 = g_edge[p + 1];
        float4 h0 = ldh4(hin + (size_t)__float_as_int(r0.x) * 128 + c);
        float4 h1 = ldh4(hin + (size_t)__float_as_int(r1.x) * 128 + c);
        acc.x += fmaxf(h0.x + r0.z * w0.x + r0.w * w1.x + bv.x, 0.f);
        acc.y += fmaxf(h0.y + r0.z * w0.y + r0.w * w1.y + bv.y, 0.f);
        acc.z += fmaxf(h0.z + r0.z * w0.z + r0.w * w1.z + bv.z, 0.f);
        acc.w += fmaxf(h0.w + r0.z * w0.w + r0.w * w1.w + bv.w, 0.f);
        acc.x += fmaxf(h1.x + r1.z * w0.x + r1.w * w1.x + bv.x, 0.f);
        acc.y += fmaxf(h1.y + r1.z * w0.y + r1.w * w1.y + bv.y, 0.f);
        acc.z += fmaxf(h1.z + r1.z * w0.z + r1.w * w1.z + bv.z, 0.f);
        acc.w += fmaxf(h1.w + r1.z * w0.w + r1.w * w1.w + bv.w, 0.f);
    }
    if (p < end) {
        float4 r = g_edge[p];
        float4 h0 = ldh4(hin + (size_t)__float_as_int(r.x) * 128 + c);
        acc.x += fmaxf(h0.x + r.z * w0.x + r.w * w1.x + bv.x, 0.f);
        acc.y += fmaxf(h0.y + r.z * w0.y + r.w * w1.y + bv.y, 0.f);
        acc.z += fmaxf(h0.z + r.z * w0.z + r.w * w1.z + bv.z, 0.f);
        acc.w += fmaxf(h0.w + r.z * w0.w + r.w * w1.w + bv.w, 0.f);
    }
    float4 hd = ldh4(hin + (size_t)row * 128 + c);
    *(float4*)(hout + (size_t)row * 128 + c) =
        make_float4(hd.x + acc.x, hd.y + acc.y, hd.z + acc.z, hd.w + acc.w);
}

// ---------------- fused MLP(+optional GELU)+LayerNorm, fp16 output ----------------
template <int K1, int GELU_OUT>
__global__ void __launch_bounds__(256, 1)
k_mlp(const float* __restrict__ in, __half* __restrict__ out,
      const float* __restrict__ Wa, const float* __restrict__ ba,
      const float* __restrict__ Wb, const float* __restrict__ bb,
      const float* __restrict__ gamma, const float* __restrict__ beta) {
    extern __shared__ float sm[];
    float* sWa = sm;                     // K1*128
    float* sWb = sWa + K1 * 128;         // 128*128
    float* sx = sWb + 128 * 128;         // 8*K1
    float* su = sx + 8 * K1;             // 8*128
    float* sred = su + 8 * 128;          // 32

    int t = threadIdx.x;
    for (int i = t; i < K1 * 128; i += 256) sWa[i] = Wa[i];
    for (int i = t; i < 128 * 128; i += 256) sWb[i] = Wb[i];

    int pr = t >> 6;
    int j = t & 63;
    int c0 = 2 * j;
    int lane = t & 31;
    int wpn = (t >> 5) & 1;

    float ba0 = ba[c0], ba1 = ba[c0 + 1];
    float bb0 = bb[c0], bb1 = bb[c0 + 1];
    float gm0 = gamma[c0], gm1 = gamma[c0 + 1];
    float bt0 = beta[c0], bt1 = beta[c0 + 1];
    __syncthreads();

    int ntiles = (NN + 7) / 8;
    for (int tile = blockIdx.x; tile < ntiles; tile += gridDim.x) {
        int nbase = tile * 8;
        __syncthreads();
        for (int i = t; i < 8 * K1; i += 256) {
            int n = nbase + i / K1;
            sx[i] = (n < NN) ? in[(size_t)n * K1 + (i % K1)] : 0.f;
        }
        __syncthreads();

        const float* x0p = sx + (2 * pr) * K1;
        const float* x1p = x0p + K1;
        float a00 = ba0, a01 = ba1, a10 = ba0, a11 = ba1;
#pragma unroll 8
        for (int k = 0; k < K1; k++) {
            float2 w = *(const float2*)(sWa + k * 128 + c0);
            float xa = x0p[k], xb = x1p[k];
            a00 += xa * w.x; a01 += xa * w.y;
            a10 += xb * w.x; a11 += xb * w.y;
        }
        a00 = gelu(a00); a01 = gelu(a01); a10 = gelu(a10); a11 = gelu(a11);
        *(float2*)(su + (2 * pr) * 128 + c0) = make_float2(a00, a01);
        *(float2*)(su + (2 * pr + 1) * 128 + c0) = make_float2(a10, a11);
        __syncthreads();

        const float* u0p = su + (2 * pr) * 128;
        const float* u1p = u0p + 128;
        float y00 = bb0, y01 = bb1, y10 = bb0, y11 = bb1;
#pragma unroll 8
        for (int k = 0; k < 128; k++) {
            float2 w = *(const float2*)(sWb + k * 128 + c0);
            float ua = u0p[k], ub = u1p[k];
            y00 += ua * w.x; y01 += ua * w.y;
            y10 += ub * w.x; y11 += ub * w.y;
        }
        if (GELU_OUT) { y00 = gelu(y00); y01 = gelu(y01); y10 = gelu(y10); y11 = gelu(y11); }

        float s0 = y00 + y01, q0 = y00 * y00 + y01 * y01;
        float s1 = y10 + y11, q1 = y10 * y10 + y11 * y11;
        for (int o = 16; o; o >>= 1) {
            s0 += __shfl_xor_sync(~0u, s0, o); q0 += __shfl_xor_sync(~0u, q0, o);
            s1 += __shfl_xor_sync(~0u, s1, o); q1 += __shfl_xor_sync(~0u, q1, o);
        }
        if (lane == 0) {
            int base = pr * 8 + wpn * 4;
            sred[base + 0] = s0; sred[base + 1] = q0;
            sred[base + 2] = s1; sred[base + 3] = q1;
        }
        __syncthreads();
        float S0 = sred[pr * 8 + 0] + sred[pr * 8 + 4];
        float Q0 = sred[pr * 8 + 1] + sred[pr * 8 + 5];
        float S1 = sred[pr * 8 + 2] + sred[pr * 8 + 6];
        float Q1 = sred[pr * 8 + 3] + sred[pr * 8 + 7];
        float mu0 = S0 * (1.f / 128.f);
        float var0 = Q0 * (1.f / 128.f) - mu0 * mu0;
        float inv0 = rsqrtf(var0 + LN_EPS);
        float mu1 = S1 * (1.f / 128.f);
        float var1 = Q1 * (1.f / 128.f) - mu1 * mu1;
        float inv1 = rsqrtf(var1 + LN_EPS);
        int n0 = nbase + 2 * pr, n1 = n0 + 1;
        if (n0 < NN) {
            float v0 = (y00 - mu0) * inv0 * gm0 + bt0;
            float v1 = (y01 - mu0) * inv0 * gm1 + bt1;
            *(__half2*)(out + (size_t)n0 * 128 + c0) = __float22half2_rn(make_float2(v0, v1));
        }
        if (n1 < NN) {
            float v0 = (y10 - mu1) * inv1 * gm0 + bt0;
            float v1 = (y11 - mu1) * inv1 * gm1 + bt1;
            *(__half2*)(out + (size_t)n1 * 128 + c0) = __float22half2_rn(make_float2(v0, v1));
        }
    }
}

// ---------------- APPNP step, fp16 state (warp per dst row) ----------------
template <int FINAL>
__global__ void __launch_bounds__(256) k_appnp16(const __half* __restrict__ cur,
                                                 __half* __restrict__ nxt,
                                                 float* __restrict__ outp,
                                                 const __half* __restrict__ x0h) {
    int gt = blockIdx.x * blockDim.x + threadIdx.x;
    int row = gt >> 5;
    if (row >= NN) return;
    int lane = gt & 31, c = 4 * lane;
    int beg = g_rowstart[row], end = g_rowstart[row + 1];
    float4 acc = make_float4(0.f, 0.f, 0.f, 0.f);
    int p = beg;
    for (; p + 2 <= end; p += 2) {
        float2 r0 = g_esw[p];
        float2 r1 = g_esw[p + 1];
        float4 h0 = ldh4(cur + (size_t)__float_as_int(r0.x) * 128 + c);
        float4 h1 = ldh4(cur + (size_t)__float_as_int(r1.x) * 128 + c);
        acc.x += r0.y * h0.x + r1.y * h1.x;
        acc.y += r0.y * h0.y + r1.y * h1.y;
        acc.z += r0.y * h0.z + r1.y * h1.z;
        acc.w += r0.y * h0.w + r1.y * h1.w;
    }
    if (p < end) {
        float2 r = g_esw[p];
        float4 h0 = ldh4(cur + (size_t)__float_as_int(r.x) * 128 + c);
        acc.x += r.y * h0.x; acc.y += r.y * h0.y;
        acc.z += r.y * h0.z; acc.w += r.y * h0.w;
    }
    float sw = g_selfw[row];
    float4 hd = ldh4(cur + (size_t)row * 128 + c);
    float4 xv = ldh4(x0h + (size_t)row * 128 + c);
    float4 o;
    o.x = 0.9f * (acc.x + sw * hd.x) + 0.1f * xv.x;
    o.y = 0.9f * (acc.y + sw * hd.y) + 0.1f * xv.y;
    o.z = 0.9f * (acc.z + sw * hd.z) + 0.1f * xv.z;
    o.w = 0.9f * (acc.w + sw * hd.w) + 0.1f * xv.w;
    if (FINAL) {
        *(float4*)(outp + (size_t)row * 128 + c) = o;
    } else {
        sth4(nxt + (size_t)row * 128 + c, o);
    }
}

// ---------------- gate MLP + segment max ----------------
__global__ void __launch_bounds__(256) k_gate(const float* __restrict__ h,
                                              const float* __restrict__ Wg1,
                                              const float* __restrict__ bg1,
                                              const float* __restrict__ Wg2,
                                              const float* __restrict__ bg2,
                                              const void* bt) {
    __shared__ float sW[128 * 64];
    __shared__ float sx[4 * 128];
    __shared__ float sred[8];
    __shared__ float sWg2[64];
    int t = threadIdx.x;
    for (int i = t; i < 128 * 64; i += 256) sW[i] = Wg1[i];
    if (t < 64) sWg2[t] = Wg2[t];
    int nd = t >> 6, j = t & 63, lane = t & 31, w2 = (t >> 5) & 1;
    float bj = bg1[j];
    float b2 = bg2[0];
    int is64 = g_is64b;
    __syncthreads();

    int ntiles = (NN + 3) / 4;
    for (int tile = blockIdx.x; tile < ntiles; tile += gridDim.x) {
        int nbase = tile * 4;
        __syncthreads();
        for (int i = t; i < 4 * 128; i += 256) {
            int n = nbase + (i >> 7);
            sx[i] = (n < NN) ? h[(size_t)n * 128 + (i & 127)] : 0.f;
        }
        __syncthreads();
        const float* xr = sx + nd * 128;
        float v = bj;
#pragma unroll 8
        for (int k = 0; k < 128; k++) v += xr[k] * sW[k * 64 + j];
        v = gelu(v) * sWg2[j];
        for (int o = 16; o; o >>= 1) v += __shfl_xor_sync(~0u, v, o);
        if (lane == 0) sred[nd * 2 + w2] = v;
        __syncthreads();
        if (j == 0) {
            int n = nbase + nd;
            if (n < NN) {
                float gate = sred[nd * 2] + sred[nd * 2 + 1] + b2;
                g_gate[n] = gate;
                int b = ldidx(bt, is64, n);
                atomicMaxF(&g_bmax[b], gate);
            }
        }
    }
}

// ---------------- softmax denom ----------------
__global__ void k_exp(const void* bt) {
    int i = blockIdx.x * blockDim.x + threadIdx.x;
    if (i >= NN) return;
    int b = ldidx(bt, g_is64b, i);
    float e = expf(g_gate[i] - g_bmax[b]);
    g_gate[i] = e;
    atomicAdd(&g_bsum[b], e);
}

// ---------------- normalize gate ----------------
__global__ void k_norm(const void* bt) {
    int i = blockIdx.x * blockDim.x + threadIdx.x;
    if (i >= NN) return;
    int b = ldidx(bt, g_is64b, i);
    g_gate[i] = g_gate[i] / g_bsum[b];
}

// ---------------- weighted pooling (batch-sorted, low atomic count) ----------------
#define GCHUNK 512
__global__ void __launch_bounds__(128) k_gagg(const float* __restrict__ h,
                                              float* __restrict__ outg,
                                              const void* bt) {
    int j = threadIdx.x;  // column 0..127
    int base = blockIdx.x * GCHUNK;
    int lim = base + GCHUNK;
    if (lim > NN) lim = NN;
    int is64 = g_is64b;
    float acc = 0.f;
    int curb = -1;
    for (int n = base; n < lim; n++) {
        int b = ldidx(bt, is64, n);
        if (b != curb) {
            if (curb >= 0) atomicAdd(&outg[curb * 128 + j], acc);
            curb = b;
            acc = 0.f;
        }
        acc += g_gate[n] * h[(size_t)n * 128 + j];
    }
    if (curb >= 0) atomicAdd(&outg[curb * 128 + j], acc);
}

// ---------------- launch ----------------
extern "C" void kernel_launch(void* const* d_in, const int* in_sizes, int n_in,
                              void* d_out, int out_size) {
    const float* x = (const float*)d_in[0];
    const void* ei = d_in[1];
    const void* bt = d_in[2];
    const float* ea = (const float*)d_in[3];
    const float* We1 = (const float*)d_in[4];  const float* be1 = (const float*)d_in[5];
    const float* W1a = (const float*)d_in[6];  const float* b1a = (const float*)d_in[7];
    const float* W1b = (const float*)d_in[8];  const float* b1b = (const float*)d_in[9];
    const float* g1  = (const float*)d_in[10]; const float* bn1 = (const float*)d_in[11];
    const float* We2 = (const float*)d_in[12]; const float* be2 = (const float*)d_in[13];
    const float* W2a = (const float*)d_in[14]; const float* b2a = (const float*)d_in[15];
    const float* W2b = (const float*)d_in[16]; const float* b2b = (const float*)d_in[17];
    const float* g2  = (const float*)d_in[18]; const float* bn2 = (const float*)d_in[19];
    const float* Wg1 = (const float*)d_in[20]; const float* bg1 = (const float*)d_in[21];
    const float* Wg2 = (const float*)d_in[22]; const float* bg2 = (const float*)d_in[23];

    float* outh = (float*)d_out;
    float* outg = outh + (size_t)NN * 128;

    float *pT0, *pB;
    __half *pA16, *pB16, *pX0h;
    cudaGetSymbolAddress((void**)&pT0, g_t0);
    cudaGetSymbolAddress((void**)&pB, g_hB);
    cudaGetSymbolAddress((void**)&pA16, g_h16A);
    cudaGetSymbolAddress((void**)&pB16, g_h16B);
    cudaGetSymbolAddress((void**)&pX0h, g_x0h);

    size_t sz1 = (size_t)(64 * 128 + 128 * 128 + 8 * 64 + 8 * 128 + 32) * sizeof(float);
    size_t sz2 = (size_t)(128 * 128 + 128 * 128 + 8 * 128 + 8 * 128 + 32) * sizeof(float);
    cudaFuncSetAttribute(k_mlp<64, 1>, cudaFuncAttributeMaxDynamicSharedMemorySize, (int)sz1);
    cudaFuncSetAttribute(k_mlp<128, 0>, cudaFuncAttributeMaxDynamicSharedMemorySize, (int)sz2);

    k_detect<<<1, 256>>>((const unsigned*)ei, (const unsigned*)bt);
    k_init<<<(NN * 32 + 255) / 256, 256>>>(outg, x);
    k_hist<<<(EE + 255) / 256, 256>>>(ei);
    k_scan_sum<<<SNB, 256>>>();
    k_scan_part<<<1, 32>>>();
    k_scan_write<<<SNB, 1024>>>();
    k_build<<<(EE + 255) / 256, 256>>>(ei, ea);

    k_conv1<<<(NN * 32 + 255) / 256, 256>>>(x, We1, be1);
    k_mlp<64, 1><<<296, 256, sz1>>>(pT0, pA16, W1a, b1a, W1b, b1b, g1, bn1);
    k_conv2<<<(NN * 32 + 255) / 256, 256>>>(pA16, pB, We2, be2);
    k_mlp<128, 0><<<296, 256, sz2>>>(pB, pX0h, W2a, b2a, W2b, b2b, g2, bn2);

    // APPNP: fp16 state, ping-pong A16/B16; x0 term from pX0h
    const __half* cur = pX0h;
    for (int it = 0; it < 15; it++) {
        __half* nxt = (it & 1) ? pB16 : pA16;
        k_appnp16<0><<<(NN * 32 + 255) / 256, 256>>>(cur, nxt, nullptr, pX0h);
        cur = nxt;
    }
    k_appnp16<1><<<(NN * 32 + 255) / 256, 256>>>(cur, nullptr, outh, pX0h);

    k_gate<<<296, 256>>>(outh, Wg1, bg1, Wg2, bg2, bt);
    k_exp<<<(NN + 255) / 256, 256>>>(bt);
    k_norm<<<(NN + 255) / 256, 256>>>(bt);
    k_gagg<<<(NN + GCHUNK - 1) / GCHUNK, 128>>>(outh, outg, bt);
}

// round 6
// speedup vs baseline: 1.7649x; 1.4133x over previous
#include <cuda_runtime.h>
#include <cuda_fp16.h>
#include <math.h>
#include <stdint.h>

#define NN 100000
#define EE 1600000
#define BB 64
#define LN_EPS 1e-5f

// ---------------- scratch (static __device__ — no allocations allowed) ----------------
static __device__ int    g_deg[NN];
static __device__ int    g_rowstart[NN + 1];
static __device__ int    g_wptr[NN];
static __device__ float  g_dis[NN];
static __device__ float  g_selfw[NN];
static __device__ float4 g_edge[EE];    // {src_as_float, w, ea0, ea1}
static __device__ float2 g_esw[EE];     // {src_as_float, w}  (slim record for APPNP)
static __device__ __half g_x16[NN * 64];       // fp16 copy of x for conv1 gathers
static __device__ __half g_t0h[NN * 64];       // conv1 out (fp16) -> mlp1 in
static __device__ __half g_hBh[NN * 128];      // conv2 out (fp16) -> mlp2 in
static __device__ __half g_h16A[NN * 128];     // mlp1 out (fp16) / APPNP ping
static __device__ __half g_h16B[NN * 128];     // APPNP pong
static __device__ __half g_x0h[NN * 128];      // mlp2 out (fp16): APPNP x0 + initial cur
static __device__ __half g_w1ah[64 * 128];
static __device__ __half g_w1bh[128 * 128];
static __device__ __half g_w2ah[128 * 128];
static __device__ __half g_w2bh[128 * 128];
static __device__ float  g_gate[NN];
static __device__ float  g_bmax[BB];
static __device__ float  g_bsum[BB];
static __device__ int    g_part[64];
static __device__ int    g_is64e, g_is64b;

// ---------------- helpers ----------------
__device__ __forceinline__ int ldidx(const void* p, int is64, long long i) {
    if (is64) return (int)((const long long*)p)[i];
    return ((const int*)p)[i];
}

__device__ __forceinline__ float gelu(float x) {
    return 0.5f * x * (1.0f + erff(x * 0.70710678118654752440f));
}

__device__ __forceinline__ void atomicMaxF(float* a, float v) {
    int* ai = (int*)a;
    int old = *ai;
    while (__int_as_float(old) < v) {
        int assumed = old;
        old = atomicCAS(ai, assumed, __float_as_int(v));
        if (old == assumed) break;
    }
}

__device__ __forceinline__ float4 ldh4(const __half* p) {
    float2 raw = *(const float2*)p;
    __half2 lo = *(__half2*)&raw.x;
    __half2 hi = *(__half2*)&raw.y;
    float2 a = __half22float2(lo), b = __half22float2(hi);
    return make_float4(a.x, a.y, b.x, b.y);
}

__device__ __forceinline__ void sth4(__half* p, float4 v) {
    __half2 lo = __float22half2_rn(make_float2(v.x, v.y));
    __half2 hi = __float22half2_rn(make_float2(v.z, v.w));
    float2 raw;
    *(__half2*)&raw.x = lo;
    *(__half2*)&raw.y = hi;
    *(float2*)p = raw;
}

// ---- mma primitives ----
__device__ __forceinline__ void ldsm_x4(uint32_t& a0, uint32_t& a1, uint32_t& a2,
                                        uint32_t& a3, uint32_t addr) {
    asm volatile("ldmatrix.sync.aligned.m8n8.x4.shared.b16 {%0,%1,%2,%3},[%4];\n"
                 : "=r"(a0), "=r"(a1), "=r"(a2), "=r"(a3) : "r"(addr));
}
__device__ __forceinline__ void ldsm_x2t(uint32_t& b0, uint32_t& b1, uint32_t addr) {
    asm volatile("ldmatrix.sync.aligned.m8n8.x2.trans.shared.b16 {%0,%1},[%2];\n"
                 : "=r"(b0), "=r"(b1) : "r"(addr));
}
__device__ __forceinline__ void mma16816(float* c, uint32_t a0, uint32_t a1, uint32_t a2,
                                         uint32_t a3, uint32_t b0, uint32_t b1) {
    asm volatile(
        "mma.sync.aligned.m16n8k16.row.col.f32.f16.f16.f32 "
        "{%0,%1,%2,%3},{%4,%5,%6,%7},{%8,%9},{%0,%1,%2,%3};\n"
        : "+f"(c[0]), "+f"(c[1]), "+f"(c[2]), "+f"(c[3])
        : "r"(a0), "r"(a1), "r"(a2), "r"(a3), "r"(b0), "r"(b1));
}

// ---------------- dtype detection ----------------
__global__ void k_detect(const unsigned* ei, const unsigned* bt) {
    __shared__ unsigned s1[256], s2[256];
    int t = threadIdx.x;
    unsigned o1 = 0, o2 = 0;
    for (int i = t; i < 2048; i += 256) {
        o1 |= ei[(long long)2 * EE - 4096 + 2 * i + 1];
        o2 |= bt[NN - 4096 + 2 * i + 1];
    }
    s1[t] = o1; s2[t] = o2;
    __syncthreads();
    for (int o = 128; o; o >>= 1) {
        if (t < o) { s1[t] |= s1[t + o]; s2[t] |= s2[t + o]; }
        __syncthreads();
    }
    if (t == 0) { g_is64e = (s1[0] == 0); g_is64b = (s2[0] == 0); }
}

// ---------------- init + x->fp16 ----------------
__global__ void k_init(float* outg, const float* __restrict__ x) {
    int i = blockIdx.x * blockDim.x + threadIdx.x;
    if (i < NN) g_deg[i] = 0;
    if (i < BB) { g_bmax[i] = __int_as_float(0xff800000); g_bsum[i] = 0.f; }
    if (i < BB * 128) outg[i] = 0.f;
    if (i == 0) g_rowstart[NN] = EE;
    if (i < NN * 32) {
        float2 v = ((const float2*)x)[i];
        ((__half2*)g_x16)[i] = __float22half2_rn(v);
    }
}

// ---------------- fp16 weight conversion ----------------
__global__ void k_cvtw(const float* W1a, const float* W1b,
                       const float* W2a, const float* W2b) {
    int i = blockIdx.x * blockDim.x + threadIdx.x;
    if (i < 64 * 128) g_w1ah[i] = __float2half(W1a[i]);
    if (i < 128 * 128) {
        g_w1bh[i] = __float2half(W1b[i]);
        g_w2ah[i] = __float2half(W2a[i]);
        g_w2bh[i] = __float2half(W2b[i]);
    }
}

// ---------------- degree histogram ----------------
__global__ void k_hist(const void* ei) {
    int e = blockIdx.x * blockDim.x + threadIdx.x;
    if (e >= EE) return;
    int d = ldidx(ei, g_is64e, (long long)EE + e);
    atomicAdd(&g_deg[d], 1);
}

// ---------------- 3-phase exclusive scan of degrees ----------------
#define SCHUNK 8192
#define SNB 13

__global__ void k_scan_sum() {
    __shared__ int sh[8];
    int b = blockIdx.x, t = threadIdx.x;
    int base = b * SCHUNK, s = 0;
    for (int i = t; i < SCHUNK; i += 256) {
        int idx = base + i;
        if (idx < NN) s += g_deg[idx];
    }
    for (int o = 16; o; o >>= 1) s += __shfl_xor_sync(~0u, s, o);
    if ((t & 31) == 0) sh[t >> 5] = s;
    __syncthreads();
    if (t == 0) {
        int v = 0;
        for (int i = 0; i < 8; i++) v += sh[i];
        g_part[b] = v;
    }
}

__global__ void k_scan_part() {
    if (threadIdx.x == 0) {
        int r = 0;
        for (int i = 0; i < SNB; i++) { int v = g_part[i]; g_part[i] = r; r += v; }
    }
}

__global__ void k_scan_write() {
    __shared__ int sh[1024];
    int b = blockIdx.x, t = threadIdx.x;
    int base = b * SCHUNK + t * 8;
    int loc[8];
    int s = 0;
#pragma unroll
    for (int j = 0; j < 8; j++) {
        int idx = base + j;
        int v = (idx < NN) ? g_deg[idx] : 0;
        loc[j] = s; s += v;
    }
    sh[t] = s;
    __syncthreads();
    for (int off = 1; off < 1024; off <<= 1) {
        int v = (t >= off) ? sh[t - off] : 0;
        __syncthreads();
        sh[t] += v;
        __syncthreads();
    }
    int off0 = g_part[b] + sh[t] - s;
#pragma unroll
    for (int j = 0; j < 8; j++) {
        int idx = base + j;
        if (idx < NN) {
            int rs = off0 + loc[j];
            g_rowstart[idx] = rs;
            g_wptr[idx] = rs;
            int d = g_deg[idx] + 1;
            g_dis[idx] = rsqrtf((float)d);
            g_selfw[idx] = 1.0f / (float)d;
        }
    }
}

// ---------------- CSR build ----------------
__global__ void k_build(const void* ei, const float* __restrict__ ea) {
    int e = blockIdx.x * blockDim.x + threadIdx.x;
    if (e >= EE) return;
    int is64 = g_is64e;
    int s = ldidx(ei, is64, e);
    int d = ldidx(ei, is64, (long long)EE + e);
    int pos = atomicAdd(&g_wptr[d], 1);
    float2 a = ((const float2*)ea)[e];
    float w = g_dis[s] * g_dis[d];
    g_edge[pos] = make_float4(__int_as_float(s), w, a.x, a.y);
    g_esw[pos] = make_float2(__int_as_float(s), w);
}

// ---------------- conv1 aggregation (64-dim, warp per dst, fp16 gathers, fp16 out) ----------------
__global__ void __launch_bounds__(256) k_conv1(const float* __restrict__ x,
                                               const float* __restrict__ We1,
                                               const float* __restrict__ be1) {
    int gt = blockIdx.x * blockDim.x + threadIdx.x;
    int row = gt >> 5;
    if (row >= NN) return;
    int lane = gt & 31, c = 2 * lane;
    float w0x = We1[c], w0y = We1[c + 1];
    float w1x = We1[64 + c], w1y = We1[64 + c + 1];
    float bx = be1[c], by = be1[c + 1];
    int beg = g_rowstart[row], end = g_rowstart[row + 1];
    float ax = 0.f, ay = 0.f;
    int p = beg;
    for (; p + 2 <= end; p += 2) {
        float4 r0 = g_edge[p];
        float4 r1 = g_edge[p + 1];
        int s0 = __float_as_int(r0.x), s1 = __float_as_int(r1.x);
        float2 xv0 = __half22float2(*(const __half2*)(g_x16 + (size_t)s0 * 64 + c));
        float2 xv1 = __half22float2(*(const __half2*)(g_x16 + (size_t)s1 * 64 + c));
        ax += fmaxf(xv0.x + r0.z * w0x + r0.w * w1x + bx, 0.f);
        ay += fmaxf(xv0.y + r0.z * w0y + r0.w * w1y + by, 0.f);
        ax += fmaxf(xv1.x + r1.z * w0x + r1.w * w1x + bx, 0.f);
        ay += fmaxf(xv1.y + r1.z * w0y + r1.w * w1y + by, 0.f);
    }
    if (p < end) {
        float4 r = g_edge[p];
        int s = __float_as_int(r.x);
        float2 xv = __half22float2(*(const __half2*)(g_x16 + (size_t)s * 64 + c));
        ax += fmaxf(xv.x + r.z * w0x + r.w * w1x + bx, 0.f);
        ay += fmaxf(xv.y + r.z * w0y + r.w * w1y + by, 0.f);
    }
    float2 xd = *(const float2*)(x + (size_t)row * 64 + c);
    *(__half2*)(g_t0h + (size_t)row * 64 + c) =
        __float22half2_rn(make_float2(ax + xd.x, ay + xd.y));
}

// ---------------- conv2 aggregation (128-dim, warp per dst, fp16 in/out) ----------------
__global__ void __launch_bounds__(256) k_conv2(const __half* __restrict__ hin,
                                               __half* __restrict__ hout,
                                               const float* __restrict__ We2,
                                               const float* __restrict__ be2) {
    int gt = blockIdx.x * blockDim.x + threadIdx.x;
    int row = gt >> 5;
    if (row >= NN) return;
    int lane = gt & 31, c = 4 * lane;
    float4 w0 = *(const float4*)(We2 + c);
    float4 w1 = *(const float4*)(We2 + 128 + c);
    float4 bv = *(const float4*)(be2 + c);
    int beg = g_rowstart[row], end = g_rowstart[row + 1];
    float4 acc = make_float4(0.f, 0.f, 0.f, 0.f);
    int p = beg;
    for (; p + 2 <= end; p += 2) {
        float4 r0 = g_edge[p];
        float4 r1 = g_edge[p + 1];
        float4 h0 = ldh4(hin + (size_t)__float_as_int(r0.x) * 128 + c);
        float4 h1 = ldh4(hin + (size_t)__float_as_int(r1.x) * 128 + c);
        acc.x += fmaxf(h0.x + r0.z * w0.x + r0.w * w1.x + bv.x, 0.f);
        acc.y += fmaxf(h0.y + r0.z * w0.y + r0.w * w1.y + bv.y, 0.f);
        acc.z += fmaxf(h0.z + r0.z * w0.z + r0.w * w1.z + bv.z, 0.f);
        acc.w += fmaxf(h0.w + r0.z * w0.w + r0.w * w1.w + bv.w, 0.f);
        acc.x += fmaxf(h1.x + r1.z * w0.x + r1.w * w1.x + bv.x, 0.f);
        acc.y += fmaxf(h1.y + r1.z * w0.y + r1.w * w1.y + bv.y, 0.f);
        acc.z += fmaxf(h1.z + r1.z * w0.z + r1.w * w1.z + bv.z, 0.f);
        acc.w += fmaxf(h1.w + r1.z * w0.w + r1.w * w1.w + bv.w, 0.f);
    }
    if (p < end) {
        float4 r = g_edge[p];
        float4 h0 = ldh4(hin + (size_t)__float_as_int(r.x) * 128 + c);
        acc.x += fmaxf(h0.x + r.z * w0.x + r.w * w1.x + bv.x, 0.f);
        acc.y += fmaxf(h0.y + r.z * w0.y + r.w * w1.y + bv.y, 0.f);
        acc.z += fmaxf(h0.z + r.z * w0.z + r.w * w1.z + bv.z, 0.f);
        acc.w += fmaxf(h0.w + r.z * w0.w + r.w * w1.w + bv.w, 0.f);
    }
    float4 hd = ldh4(hin + (size_t)row * 128 + c);
    sth4(hout + (size_t)row * 128 + c,
         make_float4(hd.x + acc.x, hd.y + acc.y, hd.z + acc.z, hd.w + acc.w));
}

// ---------------- tensor-core fused MLP(+GELU)+LayerNorm ----------------
// Block = 256 threads = 8 warps; tile = 128 nodes (16 per warp). fp16 in, fp32 acc.
template <int K1, int GELU_OUT>
__global__ void __launch_bounds__(256)
k_mlp_mma(const __half* __restrict__ in, __half* __restrict__ out,
          const __half* __restrict__ Wah, const float* __restrict__ ba,
          const __half* __restrict__ Wbh, const float* __restrict__ bb,
          const float* __restrict__ gamma, const float* __restrict__ beta) {
    extern __shared__ char smem_raw[];
    constexpr int SA_STRIDE = K1 + 8;
    __half* sWa = (__half*)smem_raw;              // [K1][136]
    __half* sWb = sWa + K1 * 136;                 // [128][136]
    __half* sA  = sWb + 128 * 136;                // [128][SA_STRIDE]
    __half* sU  = sA + 128 * SA_STRIDE;           // [128][136]
    float* sBa = (float*)(sU + 128 * 136);
    float* sBb = sBa + 128;
    float* sGm = sBb + 128;
    float* sBt = sGm + 128;

    int t = threadIdx.x;
    for (int i = t; i < K1 * 16; i += 256) {
        int r = i >> 4, ch = i & 15;
        *(uint4*)(sWa + r * 136 + ch * 8) = *(const uint4*)(Wah + r * 128 + ch * 8);
    }
    for (int i = t; i < 128 * 16; i += 256) {
        int r = i >> 4, ch = i & 15;
        *(uint4*)(sWb + r * 136 + ch * 8) = *(const uint4*)(Wbh + r * 128 + ch * 8);
    }
    if (t < 128) { sBa[t] = ba[t]; sBb[t] = bb[t]; sGm[t] = gamma[t]; sBt[t] = beta[t]; }

    int nbase = blockIdx.x * 128;
    constexpr int CH = K1 / 8;
    for (int i = t; i < 128 * CH; i += 256) {
        int r = i / CH, ch = i % CH;
        int node = nbase + r;
        uint4 v = make_uint4(0, 0, 0, 0);
        if (node < NN) v = *(const uint4*)(in + (size_t)node * K1 + ch * 8);
        *(uint4*)(sA + r * SA_STRIDE + ch * 8) = v;
    }
    __syncthreads();

    int warp = t >> 5, lane = t & 31;
    int mbase = warp * 16;
    uint32_t sA_b = (uint32_t)__cvta_generic_to_shared(sA);
    uint32_t sWa_b = (uint32_t)__cvta_generic_to_shared(sWa);
    uint32_t sWb_b = (uint32_t)__cvta_generic_to_shared(sWb);

    float c[16][4];

    // ---- GEMM1: sA[16 x K1] @ sWa[K1 x 128] ----
#pragma unroll
    for (int nt = 0; nt < 16; nt++) { c[nt][0] = c[nt][1] = c[nt][2] = c[nt][3] = 0.f; }
#pragma unroll
    for (int ks = 0; ks < K1 / 16; ks++) {
        uint32_t a0, a1, a2, a3;
        uint32_t aaddr = sA_b +
            (((mbase + (lane & 15)) * SA_STRIDE + ks * 16 + ((lane >> 4) << 3)) << 1);
        ldsm_x4(a0, a1, a2, a3, aaddr);
#pragma unroll
        for (int nt = 0; nt < 16; nt++) {
            uint32_t b0, b1;
            uint32_t baddr = sWa_b + (((ks * 16 + (lane & 15)) * 136 + nt * 8) << 1);
            ldsm_x2t(b0, b1, baddr);
            mma16816(c[nt], a0, a1, a2, a3, b0, b1);
        }
    }
    // epilogue1: bias + GELU -> sU fp16
    {
        int r0 = lane >> 2;
#pragma unroll
        for (int nt = 0; nt < 16; nt++) {
            int col0 = nt * 8 + (lane & 3) * 2;
            float u00 = gelu(c[nt][0] + sBa[col0]);
            float u01 = gelu(c[nt][1] + sBa[col0 + 1]);
            float u10 = gelu(c[nt][2] + sBa[col0]);
            float u11 = gelu(c[nt][3] + sBa[col0 + 1]);
            *(__half2*)(sU + (mbase + r0) * 136 + col0) =
                __float22half2_rn(make_float2(u00, u01));
            *(__half2*)(sU + (mbase + r0 + 8) * 136 + col0) =
                __float22half2_rn(make_float2(u10, u11));
        }
    }
    __syncwarp();
    uint32_t sU_b = (uint32_t)__cvta_generic_to_shared(sU);

    // ---- GEMM2: sU[16 x 128] @ sWb[128 x 128] ----
#pragma unroll
    for (int nt = 0; nt < 16; nt++) { c[nt][0] = c[nt][1] = c[nt][2] = c[nt][3] = 0.f; }
#pragma unroll
    for (int ks = 0; ks < 8; ks++) {
        uint32_t a0, a1, a2, a3;
        uint32_t aaddr = sU_b +
            (((mbase + (lane & 15)) * 136 + ks * 16 + ((lane >> 4) << 3)) << 1);
        ldsm_x4(a0, a1, a2, a3, aaddr);
#pragma unroll
        for (int nt = 0; nt < 16; nt++) {
            uint32_t b0, b1;
            uint32_t baddr = sWb_b + (((ks * 16 + (lane & 15)) * 136 + nt * 8) << 1);
            ldsm_x2t(b0, b1, baddr);
            mma16816(c[nt], a0, a1, a2, a3, b0, b1);
        }
    }

    // epilogue2: bias (+GELU) + LayerNorm, write fp16 out
    {
        int r0 = lane >> 2;
        float s0 = 0.f, q0 = 0.f, s1 = 0.f, q1 = 0.f;
#pragma unroll
        for (int nt = 0; nt < 16; nt++) {
            int col0 = nt * 8 + (lane & 3) * 2;
            float y00 = c[nt][0] + sBb[col0];
            float y01 = c[nt][1] + sBb[col0 + 1];
            float y10 = c[nt][2] + sBb[col0];
            float y11 = c[nt][3] + sBb[col0 + 1];
            if (GELU_OUT) { y00 = gelu(y00); y01 = gelu(y01); y10 = gelu(y10); y11 = gelu(y11); }
            c[nt][0] = y00; c[nt][1] = y01; c[nt][2] = y10; c[nt][3] = y11;
            s0 += y00 + y01; q0 += y00 * y00 + y01 * y01;
            s1 += y10 + y11; q1 += y10 * y10 + y11 * y11;
        }
#pragma unroll
        for (int o = 1; o <= 2; o <<= 1) {
            s0 += __shfl_xor_sync(~0u, s0, o); q0 += __shfl_xor_sync(~0u, q0, o);
            s1 += __shfl_xor_sync(~0u, s1, o); q1 += __shfl_xor_sync(~0u, q1, o);
        }
        float mu0 = s0 * (1.f / 128.f);
        float inv0 = rsqrtf(q0 * (1.f / 128.f) - mu0 * mu0 + LN_EPS);
        float mu1 = s1 * (1.f / 128.f);
        float inv1 = rsqrtf(q1 * (1.f / 128.f) - mu1 * mu1 + LN_EPS);
        int node0 = nbase + mbase + r0;
        int node1 = node0 + 8;
#pragma unroll
        for (int nt = 0; nt < 16; nt++) {
            int col0 = nt * 8 + (lane & 3) * 2;
            float gm0 = sGm[col0], gm1 = sGm[col0 + 1];
            float bt0 = sBt[col0], bt1 = sBt[col0 + 1];
            if (node0 < NN) {
                *(__half2*)(out + (size_t)node0 * 128 + col0) = __float22half2_rn(
                    make_float2((c[nt][0] - mu0) * inv0 * gm0 + bt0,
                                (c[nt][1] - mu0) * inv0 * gm1 + bt1));
            }
            if (node1 < NN) {
                *(__half2*)(out + (size_t)node1 * 128 + col0) = __float22half2_rn(
                    make_float2((c[nt][2] - mu1) * inv1 * gm0 + bt0,
                                (c[nt][3] - mu1) * inv1 * gm1 + bt1));
            }
        }
    }
}

// ---------------- APPNP step, fp16 state (warp per dst row, unroll 4) ----------------
template <int FINAL>
__global__ void __launch_bounds__(256) k_appnp16(const __half* __restrict__ cur,
                                                 __half* __restrict__ nxt,
                                                 float* __restrict__ outp,
                                                 const __half* __restrict__ x0h) {
    int gt = blockIdx.x * blockDim.x + threadIdx.x;
    int row = gt >> 5;
    if (row >= NN) return;
    int lane = gt & 31, c = 4 * lane;
    int beg = g_rowstart[row], end = g_rowstart[row + 1];
    float4 acc = make_float4(0.f, 0.f, 0.f, 0.f);
    int p = beg;
    for (; p + 4 <= end; p += 4) {
        float2 r0 = g_esw[p];
        float2 r1 = g_esw[p + 1];
        float2 r2 = g_esw[p + 2];
        float2 r3 = g_esw[p + 3];
        float4 h0 = ldh4(cur + (size_t)__float_as_int(r0.x) * 128 + c);
        float4 h1 = ldh4(cur + (size_t)__float_as_int(r1.x) * 128 + c);
        float4 h2 = ldh4(cur + (size_t)__float_as_int(r2.x) * 128 + c);
        float4 h3 = ldh4(cur + (size_t)__float_as_int(r3.x) * 128 + c);
        acc.x += r0.y * h0.x + r1.y * h1.x + r2.y * h2.x + r3.y * h3.x;
        acc.y += r0.y * h0.y + r1.y * h1.y + r2.y * h2.y + r3.y * h3.y;
        acc.z += r0.y * h0.z + r1.y * h1.z + r2.y * h2.z + r3.y * h3.z;
        acc.w += r0.y * h0.w + r1.y * h1.w + r2.y * h2.w + r3.y * h3.w;
    }
    for (; p < end; p++) {
        float2 r = g_esw[p];
        float4 h0 = ldh4(cur + (size_t)__float_as_int(r.x) * 128 + c);
        acc.x += r.y * h0.x; acc.y += r.y * h0.y;
        acc.z += r.y * h0.z; acc.w += r.y * h0.w;
    }
    float sw = g_selfw[row];
    float4 hd = ldh4(cur + (size_t)row * 128 + c);
    float4 xv = ldh4(x0h + (size_t)row * 128 + c);
    float4 o;
    o.x = 0.9f * (acc.x + sw * hd.x) + 0.1f * xv.x;
    o.y = 0.9f * (acc.y + sw * hd.y) + 0.1f * xv.y;
    o.z = 0.9f * (acc.z + sw * hd.z) + 0.1f * xv.z;
    o.w = 0.9f * (acc.w + sw * hd.w) + 0.1f * xv.w;
    if (FINAL) {
        *(float4*)(outp + (size_t)row * 128 + c) = o;
    } else {
        sth4(nxt + (size_t)row * 128 + c, o);
    }
}

// ---------------- gate MLP + segment max ----------------
__global__ void __launch_bounds__(256) k_gate(const float* __restrict__ h,
                                              const float* __restrict__ Wg1,
                                              const float* __restrict__ bg1,
                                              const float* __restrict__ Wg2,
                                              const float* __restrict__ bg2,
                                              const void* bt) {
    __shared__ float sW[128 * 64];
    __shared__ float sx[4 * 128];
    __shared__ float sred[8];
    __shared__ float sWg2[64];
    int t = threadIdx.x;
    for (int i = t; i < 128 * 64; i += 256) sW[i] = Wg1[i];
    if (t < 64) sWg2[t] = Wg2[t];
    int nd = t >> 6, j = t & 63, lane = t & 31, w2 = (t >> 5) & 1;
    float bj = bg1[j];
    float b2 = bg2[0];
    int is64 = g_is64b;
    __syncthreads();

    int ntiles = (NN + 3) / 4;
    for (int tile = blockIdx.x; tile < ntiles; tile += gridDim.x) {
        int nbase = tile * 4;
        __syncthreads();
        for (int i = t; i < 4 * 128; i += 256) {
            int n = nbase + (i >> 7);
            sx[i] = (n < NN) ? h[(size_t)n * 128 + (i & 127)] : 0.f;
        }
        __syncthreads();
        const float* xr = sx + nd * 128;
        float v = bj;
#pragma unroll 8
        for (int k = 0; k < 128; k++) v += xr[k] * sW[k * 64 + j];
        v = gelu(v) * sWg2[j];
        for (int o = 16; o; o >>= 1) v += __shfl_xor_sync(~0u, v, o);
        if (lane == 0) sred[nd * 2 + w2] = v;
        __syncthreads();
        if (j == 0) {
            int n = nbase + nd;
            if (n < NN) {
                float gate = sred[nd * 2] + sred[nd * 2 + 1] + b2;
                g_gate[n] = gate;
                int b = ldidx(bt, is64, n);
                atomicMaxF(&g_bmax[b], gate);
            }
        }
    }
}

// ---------------- softmax denom ----------------
__global__ void k_exp(const void* bt) {
    int i = blockIdx.x * blockDim.x + threadIdx.x;
    if (i >= NN) return;
    int b = ldidx(bt, g_is64b, i);
    float e = expf(g_gate[i] - g_bmax[b]);
    g_gate[i] = e;
    atomicAdd(&g_bsum[b], e);
}

// ---------------- normalize gate ----------------
__global__ void k_norm(const void* bt) {
    int i = blockIdx.x * blockDim.x + threadIdx.x;
    if (i >= NN) return;
    int b = ldidx(bt, g_is64b, i);
    g_gate[i] = g_gate[i] / g_bsum[b];
}

// ---------------- weighted pooling (batch-sorted, low atomic count) ----------------
#define GCHUNK 512
__global__ void __launch_bounds__(128) k_gagg(const float* __restrict__ h,
                                              float* __restrict__ outg,
                                              const void* bt) {
    int j = threadIdx.x;
    int base = blockIdx.x * GCHUNK;
    int lim = base + GCHUNK;
    if (lim > NN) lim = NN;
    int is64 = g_is64b;
    float acc = 0.f;
    int curb = -1;
    for (int n = base; n < lim; n++) {
        int b = ldidx(bt, is64, n);
        if (b != curb) {
            if (curb >= 0) atomicAdd(&outg[curb * 128 + j], acc);
            curb = b;
            acc = 0.f;
        }
        acc += g_gate[n] * h[(size_t)n * 128 + j];
    }
    if (curb >= 0) atomicAdd(&outg[curb * 128 + j], acc);
}

// ---------------- launch ----------------
extern "C" void kernel_launch(void* const* d_in, const int* in_sizes, int n_in,
                              void* d_out, int out_size) {
    const float* x = (const float*)d_in[0];
    const void* ei = d_in[1];
    const void* bt = d_in[2];
    const float* ea = (const float*)d_in[3];
    const float* We1 = (const float*)d_in[4];  const float* be1 = (const float*)d_in[5];
    const float* W1a = (const float*)d_in[6];  const float* b1a = (const float*)d_in[7];
    const float* W1b = (const float*)d_in[8];  const float* b1b = (const float*)d_in[9];
    const float* g1  = (const float*)d_in[10]; const float* bn1 = (const float*)d_in[11];
    const float* We2 = (const float*)d_in[12]; const float* be2 = (const float*)d_in[13];
    const float* W2a = (const float*)d_in[14]; const float* b2a = (const float*)d_in[15];
    const float* W2b = (const float*)d_in[16]; const float* b2b = (const float*)d_in[17];
    const float* g2  = (const float*)d_in[18]; const float* bn2 = (const float*)d_in[19];
    const float* Wg1 = (const float*)d_in[20]; const float* bg1 = (const float*)d_in[21];
    const float* Wg2 = (const float*)d_in[22]; const float* bg2 = (const float*)d_in[23];

    float* outh = (float*)d_out;
    float* outg = outh + (size_t)NN * 128;

    __half *pT0h, *pHBh, *pA16, *pB16, *pX0h, *pW1ah, *pW1bh, *pW2ah, *pW2bh;
    cudaGetSymbolAddress((void**)&pT0h, g_t0h);
    cudaGetSymbolAddress((void**)&pHBh, g_hBh);
    cudaGetSymbolAddress((void**)&pA16, g_h16A);
    cudaGetSymbolAddress((void**)&pB16, g_h16B);
    cudaGetSymbolAddress((void**)&pX0h, g_x0h);
    cudaGetSymbolAddress((void**)&pW1ah, g_w1ah);
    cudaGetSymbolAddress((void**)&pW1bh, g_w1bh);
    cudaGetSymbolAddress((void**)&pW2ah, g_w2ah);
    cudaGetSymbolAddress((void**)&pW2bh, g_w2bh);

    // dynamic smem sizes for mma MLPs
    size_t sz1 = (size_t)(64 * 136 + 128 * 136 + 128 * 72 + 128 * 136) * 2 + 4 * 128 * 4;
    size_t sz2 = (size_t)(128 * 136 + 128 * 136 + 128 * 136 + 128 * 136) * 2 + 4 * 128 * 4;
    cudaFuncSetAttribute(k_mlp_mma<64, 1>, cudaFuncAttributeMaxDynamicSharedMemorySize, (int)sz1);
    cudaFuncSetAttribute(k_mlp_mma<128, 0>, cudaFuncAttributeMaxDynamicSharedMemorySize, (int)sz2);

    k_detect<<<1, 256>>>((const unsigned*)ei, (const unsigned*)bt);
    k_init<<<(NN * 32 + 255) / 256, 256>>>(outg, x);
    k_cvtw<<<64, 256>>>(W1a, W1b, W2a, W2b);
    k_hist<<<(EE + 255) / 256, 256>>>(ei);
    k_scan_sum<<<SNB, 256>>>();
    k_scan_part<<<1, 32>>>();
    k_scan_write<<<SNB, 1024>>>();
    k_build<<<(EE + 255) / 256, 256>>>(ei, ea);

    int ntile = (NN + 127) / 128;
    k_conv1<<<(NN * 32 + 255) / 256, 256>>>(x, We1, be1);
    k_mlp_mma<64, 1><<<ntile, 256, sz1>>>(pT0h, pA16, pW1ah, b1a, pW1bh, b1b, g1, bn1);
    k_conv2<<<(NN * 32 + 255) / 256, 256>>>(pA16, pHBh, We2, be2);
    k_mlp_mma<128, 0><<<ntile, 256, sz2>>>(pHBh, pX0h, pW2ah, b2a, pW2bh, b2b, g2, bn2);

    // APPNP: fp16 state, ping-pong A16/B16; x0 term from pX0h
    const __half* cur = pX0h;
    for (int it = 0; it < 15; it++) {
        __half* nxt = (it & 1) ? pB16 : pA16;
        k_appnp16<0><<<(NN * 32 + 255) / 256, 256>>>(cur, nxt, nullptr, pX0h);
        cur = nxt;
    }
    k_appnp16<1><<<(NN * 32 + 255) / 256, 256>>>(cur, nullptr, outh, pX0h);

    k_gate<<<296, 256>>>(outh, Wg1, bg1, Wg2, bg2, bt);
    k_exp<<<(NN + 255) / 256, 256>>>(bt);
    k_norm<<<(NN + 255) / 256, 256>>>(bt);
    k_gagg<<<(NN + GCHUNK - 1) / GCHUNK, 128>>>(outh, outg, bt);
}

// round 7
// speedup vs baseline: 1.8417x; 1.0435x over previous
#include <cuda_runtime.h>
#include <cuda_fp16.h>
#include <math.h>
#include <stdint.h>

#define NN 100000
#define EE 1600000
#define BB 64
#define LN_EPS 1e-5f

// ---------------- scratch ----------------
static __device__ int    g_deg[NN];
static __device__ int    g_rowstart[NN + 1];
static __device__ int    g_wptr[NN];
static __device__ float  g_dis[NN];
static __device__ float  g_selfw[NN];
static __device__ float4 g_edge[EE];    // {src_as_float, w, ea0, ea1}
static __device__ float2 g_esw[EE];     // {src_as_float, w}
static __device__ __half g_x16[NN * 64];
static __device__ __half g_t0h[NN * 64];
static __device__ __half g_hBh[NN * 128];
static __device__ __half g_h16A[NN * 128];
static __device__ __half g_h16B[NN * 128];
static __device__ __half g_x0h[NN * 128];
static __device__ __half g_w1ah[64 * 128];
static __device__ __half g_w1bh[128 * 128];
static __device__ __half g_w2ah[128 * 128];
static __device__ __half g_w2bh[128 * 128];
static __device__ float  g_gate[NN];
static __device__ float  g_bmax[BB];
static __device__ float  g_bsum[BB];
static __device__ int    g_part[64];
static __device__ int    g_is64e, g_is64b;

// ---------------- helpers ----------------
__device__ __forceinline__ int ldidx(const void* p, int is64, long long i) {
    if (is64) return (int)((const long long*)p)[i];
    return ((const int*)p)[i];
}

__device__ __forceinline__ float gelu(float x) {
    return 0.5f * x * (1.0f + erff(x * 0.70710678118654752440f));
}

__device__ __forceinline__ void atomicMaxF(float* a, float v) {
    int* ai = (int*)a;
    int old = *ai;
    while (__int_as_float(old) < v) {
        int assumed = old;
        old = atomicCAS(ai, assumed, __float_as_int(v));
        if (old == assumed) break;
    }
}

__device__ __forceinline__ float4 ldh4(const __half* p) {
    float2 raw = *(const float2*)p;
    __half2 lo = *(__half2*)&raw.x;
    __half2 hi = *(__half2*)&raw.y;
    float2 a = __half22float2(lo), b = __half22float2(hi);
    return make_float4(a.x, a.y, b.x, b.y);
}

// 8-wide fp16 helpers (uint4 = 8 halves)
__device__ __forceinline__ void fma8(float2 a[4], uint4 v, float w) {
    float2 f0 = __half22float2(*(__half2*)&v.x);
    float2 f1 = __half22float2(*(__half2*)&v.y);
    float2 f2 = __half22float2(*(__half2*)&v.z);
    float2 f3 = __half22float2(*(__half2*)&v.w);
    a[0].x += w * f0.x; a[0].y += w * f0.y;
    a[1].x += w * f1.x; a[1].y += w * f1.y;
    a[2].x += w * f2.x; a[2].y += w * f2.y;
    a[3].x += w * f3.x; a[3].y += w * f3.y;
}

// ---- mma primitives ----
__device__ __forceinline__ void ldsm_x4(uint32_t& a0, uint32_t& a1, uint32_t& a2,
                                        uint32_t& a3, uint32_t addr) {
    asm volatile("ldmatrix.sync.aligned.m8n8.x4.shared.b16 {%0,%1,%2,%3},[%4];\n"
                 : "=r"(a0), "=r"(a1), "=r"(a2), "=r"(a3) : "r"(addr));
}
__device__ __forceinline__ void ldsm_x2t(uint32_t& b0, uint32_t& b1, uint32_t addr) {
    asm volatile("ldmatrix.sync.aligned.m8n8.x2.trans.shared.b16 {%0,%1},[%2];\n"
                 : "=r"(b0), "=r"(b1) : "r"(addr));
}
__device__ __forceinline__ void mma16816(float* c, uint32_t a0, uint32_t a1, uint32_t a2,
                                         uint32_t a3, uint32_t b0, uint32_t b1) {
    asm volatile(
        "mma.sync.aligned.m16n8k16.row.col.f32.f16.f16.f32 "
        "{%0,%1,%2,%3},{%4,%5,%6,%7},{%8,%9},{%0,%1,%2,%3};\n"
        : "+f"(c[0]), "+f"(c[1]), "+f"(c[2]), "+f"(c[3])
        : "r"(a0), "r"(a1), "r"(a2), "r"(a3), "r"(b0), "r"(b1));
}

// ---------------- dtype detection ----------------
__global__ void k_detect(const unsigned* ei, const unsigned* bt) {
    __shared__ unsigned s1[256], s2[256];
    int t = threadIdx.x;
    unsigned o1 = 0, o2 = 0;
    for (int i = t; i < 2048; i += 256) {
        o1 |= ei[(long long)2 * EE - 4096 + 2 * i + 1];
        o2 |= bt[NN - 4096 + 2 * i + 1];
    }
    s1[t] = o1; s2[t] = o2;
    __syncthreads();
    for (int o = 128; o; o >>= 1) {
        if (t < o) { s1[t] |= s1[t + o]; s2[t] |= s2[t + o]; }
        __syncthreads();
    }
    if (t == 0) { g_is64e = (s1[0] == 0); g_is64b = (s2[0] == 0); }
}

// ---------------- init + x->fp16 ----------------
__global__ void k_init(float* outg, const float* __restrict__ x) {
    int i = blockIdx.x * blockDim.x + threadIdx.x;
    if (i < NN) g_deg[i] = 0;
    if (i < BB) { g_bmax[i] = __int_as_float(0xff800000); g_bsum[i] = 0.f; }
    if (i < BB * 128) outg[i] = 0.f;
    if (i == 0) g_rowstart[NN] = EE;
    if (i < NN * 32) {
        float2 v = ((const float2*)x)[i];
        ((__half2*)g_x16)[i] = __float22half2_rn(v);
    }
}

// ---------------- fp16 weight conversion ----------------
__global__ void k_cvtw(const float* W1a, const float* W1b,
                       const float* W2a, const float* W2b) {
    int i = blockIdx.x * blockDim.x + threadIdx.x;
    if (i < 64 * 128) g_w1ah[i] = __float2half(W1a[i]);
    if (i < 128 * 128) {
        g_w1bh[i] = __float2half(W1b[i]);
        g_w2ah[i] = __float2half(W2a[i]);
        g_w2bh[i] = __float2half(W2b[i]);
    }
}

// ---------------- degree histogram ----------------
__global__ void k_hist(const void* ei) {
    int e = blockIdx.x * blockDim.x + threadIdx.x;
    if (e >= EE) return;
    int d = ldidx(ei, g_is64e, (long long)EE + e);
    atomicAdd(&g_deg[d], 1);
}

// ---------------- 3-phase exclusive scan ----------------
#define SCHUNK 8192
#define SNB 13

__global__ void k_scan_sum() {
    __shared__ int sh[8];
    int b = blockIdx.x, t = threadIdx.x;
    int base = b * SCHUNK, s = 0;
    for (int i = t; i < SCHUNK; i += 256) {
        int idx = base + i;
        if (idx < NN) s += g_deg[idx];
    }
    for (int o = 16; o; o >>= 1) s += __shfl_xor_sync(~0u, s, o);
    if ((t & 31) == 0) sh[t >> 5] = s;
    __syncthreads();
    if (t == 0) {
        int v = 0;
        for (int i = 0; i < 8; i++) v += sh[i];
        g_part[b] = v;
    }
}

__global__ void k_scan_part() {
    if (threadIdx.x == 0) {
        int r = 0;
        for (int i = 0; i < SNB; i++) { int v = g_part[i]; g_part[i] = r; r += v; }
    }
}

__global__ void k_scan_write() {
    __shared__ int sh[1024];
    int b = blockIdx.x, t = threadIdx.x;
    int base = b * SCHUNK + t * 8;
    int loc[8];
    int s = 0;
#pragma unroll
    for (int j = 0; j < 8; j++) {
        int idx = base + j;
        int v = (idx < NN) ? g_deg[idx] : 0;
        loc[j] = s; s += v;
    }
    sh[t] = s;
    __syncthreads();
    for (int off = 1; off < 1024; off <<= 1) {
        int v = (t >= off) ? sh[t - off] : 0;
        __syncthreads();
        sh[t] += v;
        __syncthreads();
    }
    int off0 = g_part[b] + sh[t] - s;
#pragma unroll
    for (int j = 0; j < 8; j++) {
        int idx = base + j;
        if (idx < NN) {
            int rs = off0 + loc[j];
            g_rowstart[idx] = rs;
            g_wptr[idx] = rs;
            int d = g_deg[idx] + 1;
            g_dis[idx] = rsqrtf((float)d);
            g_selfw[idx] = 1.0f / (float)d;
        }
    }
}

// ---------------- CSR build ----------------
__global__ void k_build(const void* ei, const float* __restrict__ ea) {
    int e = blockIdx.x * blockDim.x + threadIdx.x;
    if (e >= EE) return;
    int is64 = g_is64e;
    int s = ldidx(ei, is64, e);
    int d = ldidx(ei, is64, (long long)EE + e);
    int pos = atomicAdd(&g_wptr[d], 1);
    float2 a = ((const float2*)ea)[e];
    float w = g_dis[s] * g_dis[d];
    g_edge[pos] = make_float4(__int_as_float(s), w, a.x, a.y);
    g_esw[pos] = make_float2(__int_as_float(s), w);
}

// ---------------- conv1 (64-dim, warp per dst) ----------------
__global__ void __launch_bounds__(256) k_conv1(const float* __restrict__ x,
                                               const float* __restrict__ We1,
                                               const float* __restrict__ be1) {
    int gt = blockIdx.x * blockDim.x + threadIdx.x;
    int row = gt >> 5;
    if (row >= NN) return;
    int lane = gt & 31, c = 2 * lane;
    float w0x = We1[c], w0y = We1[c + 1];
    float w1x = We1[64 + c], w1y = We1[64 + c + 1];
    float bx = be1[c], by = be1[c + 1];
    int beg = g_rowstart[row], end = g_rowstart[row + 1];
    float ax = 0.f, ay = 0.f;
    int p = beg;
    for (; p + 2 <= end; p += 2) {
        float4 r0 = g_edge[p];
        float4 r1 = g_edge[p + 1];
        int s0 = __float_as_int(r0.x), s1 = __float_as_int(r1.x);
        float2 xv0 = __half22float2(*(const __half2*)(g_x16 + (size_t)s0 * 64 + c));
        float2 xv1 = __half22float2(*(const __half2*)(g_x16 + (size_t)s1 * 64 + c));
        ax += fmaxf(xv0.x + r0.z * w0x + r0.w * w1x + bx, 0.f);
        ay += fmaxf(xv0.y + r0.z * w0y + r0.w * w1y + by, 0.f);
        ax += fmaxf(xv1.x + r1.z * w0x + r1.w * w1x + bx, 0.f);
        ay += fmaxf(xv1.y + r1.z * w0y + r1.w * w1y + by, 0.f);
    }
    if (p < end) {
        float4 r = g_edge[p];
        int s = __float_as_int(r.x);
        float2 xv = __half22float2(*(const __half2*)(g_x16 + (size_t)s * 64 + c));
        ax += fmaxf(xv.x + r.z * w0x + r.w * w1x + bx, 0.f);
        ay += fmaxf(xv.y + r.z * w0y + r.w * w1y + by, 0.f);
    }
    float2 xd = *(const float2*)(x + (size_t)row * 64 + c);
    *(__half2*)(g_t0h + (size_t)row * 64 + c) =
        __float22half2_rn(make_float2(ax + xd.x, ay + xd.y));
}

// ---------------- conv2 (128-dim, 2 rows/warp, 16 lanes x 8 cols) ----------------
__global__ void __launch_bounds__(256) k_conv2(const __half* __restrict__ hin,
                                               __half* __restrict__ hout,
                                               const float* __restrict__ We2,
                                               const float* __restrict__ be2) {
    int gwarp = (blockIdx.x * blockDim.x + threadIdx.x) >> 5;
    int lane = threadIdx.x & 31;
    int row = gwarp * 2 + (lane >> 4);
    if (row >= NN) return;
    int li = lane & 15, c = li * 8;
    float4 w0a = *(const float4*)(We2 + c);
    float4 w0b = *(const float4*)(We2 + c + 4);
    float4 w1a = *(const float4*)(We2 + 128 + c);
    float4 w1b = *(const float4*)(We2 + 128 + c + 4);
    float4 bva = *(const float4*)(be2 + c);
    float4 bvb = *(const float4*)(be2 + c + 4);
    int beg = g_rowstart[row], end = g_rowstart[row + 1];
    float2 acc[4] = {{0.f, 0.f}, {0.f, 0.f}, {0.f, 0.f}, {0.f, 0.f}};
    for (int p = beg; p < end; p++) {
        float4 r = g_edge[p];
        uint4 v = *(const uint4*)(hin + (size_t)__float_as_int(r.x) * 128 + c);
        float2 f0 = __half22float2(*(__half2*)&v.x);
        float2 f1 = __half22float2(*(__half2*)&v.y);
        float2 f2 = __half22float2(*(__half2*)&v.z);
        float2 f3 = __half22float2(*(__half2*)&v.w);
        acc[0].x += fmaxf(f0.x + r.z * w0a.x + r.w * w1a.x + bva.x, 0.f);
        acc[0].y += fmaxf(f0.y + r.z * w0a.y + r.w * w1a.y + bva.y, 0.f);
        acc[1].x += fmaxf(f1.x + r.z * w0a.z + r.w * w1a.z + bva.z, 0.f);
        acc[1].y += fmaxf(f1.y + r.z * w0a.w + r.w * w1a.w + bva.w, 0.f);
        acc[2].x += fmaxf(f2.x + r.z * w0b.x + r.w * w1b.x + bvb.x, 0.f);
        acc[2].y += fmaxf(f2.y + r.z * w0b.y + r.w * w1b.y + bvb.y, 0.f);
        acc[3].x += fmaxf(f3.x + r.z * w0b.z + r.w * w1b.z + bvb.z, 0.f);
        acc[3].y += fmaxf(f3.y + r.z * w0b.w + r.w * w1b.w + bvb.w, 0.f);
    }
    uint4 hd = *(const uint4*)(hin + (size_t)row * 128 + c);
    float2 d0 = __half22float2(*(__half2*)&hd.x);
    float2 d1 = __half22float2(*(__half2*)&hd.y);
    float2 d2 = __half22float2(*(__half2*)&hd.z);
    float2 d3 = __half22float2(*(__half2*)&hd.w);
    uint4 o;
    *(__half2*)&o.x = __float22half2_rn(make_float2(d0.x + acc[0].x, d0.y + acc[0].y));
    *(__half2*)&o.y = __float22half2_rn(make_float2(d1.x + acc[1].x, d1.y + acc[1].y));
    *(__half2*)&o.z = __float22half2_rn(make_float2(d2.x + acc[2].x, d2.y + acc[2].y));
    *(__half2*)&o.w = __float22half2_rn(make_float2(d3.x + acc[3].x, d3.y + acc[3].y));
    *(uint4*)(hout + (size_t)row * 128 + c) = o;
}

// ---------------- tensor-core fused MLP(+GELU)+LayerNorm ----------------
template <int K1, int GELU_OUT>
__global__ void __launch_bounds__(256)
k_mlp_mma(const __half* __restrict__ in, __half* __restrict__ out,
          const __half* __restrict__ Wah, const float* __restrict__ ba,
          const __half* __restrict__ Wbh, const float* __restrict__ bb,
          const float* __restrict__ gamma, const float* __restrict__ beta) {
    extern __shared__ char smem_raw[];
    constexpr int SA_STRIDE = K1 + 8;
    __half* sWa = (__half*)smem_raw;
    __half* sWb = sWa + K1 * 136;
    __half* sA  = sWb + 128 * 136;
    __half* sU  = sA + 128 * SA_STRIDE;
    float* sBa = (float*)(sU + 128 * 136);
    float* sBb = sBa + 128;
    float* sGm = sBb + 128;
    float* sBt = sGm + 128;

    int t = threadIdx.x;
    for (int i = t; i < K1 * 16; i += 256) {
        int r = i >> 4, ch = i & 15;
        *(uint4*)(sWa + r * 136 + ch * 8) = *(const uint4*)(Wah + r * 128 + ch * 8);
    }
    for (int i = t; i < 128 * 16; i += 256) {
        int r = i >> 4, ch = i & 15;
        *(uint4*)(sWb + r * 136 + ch * 8) = *(const uint4*)(Wbh + r * 128 + ch * 8);
    }
    if (t < 128) { sBa[t] = ba[t]; sBb[t] = bb[t]; sGm[t] = gamma[t]; sBt[t] = beta[t]; }

    int nbase = blockIdx.x * 128;
    constexpr int CH = K1 / 8;
    for (int i = t; i < 128 * CH; i += 256) {
        int r = i / CH, ch = i % CH;
        int node = nbase + r;
        uint4 v = make_uint4(0, 0, 0, 0);
        if (node < NN) v = *(const uint4*)(in + (size_t)node * K1 + ch * 8);
        *(uint4*)(sA + r * SA_STRIDE + ch * 8) = v;
    }
    __syncthreads();

    int warp = t >> 5, lane = t & 31;
    int mbase = warp * 16;
    uint32_t sA_b = (uint32_t)__cvta_generic_to_shared(sA);
    uint32_t sWa_b = (uint32_t)__cvta_generic_to_shared(sWa);
    uint32_t sWb_b = (uint32_t)__cvta_generic_to_shared(sWb);

    float c[16][4];

#pragma unroll
    for (int nt = 0; nt < 16; nt++) { c[nt][0] = c[nt][1] = c[nt][2] = c[nt][3] = 0.f; }
#pragma unroll
    for (int ks = 0; ks < K1 / 16; ks++) {
        uint32_t a0, a1, a2, a3;
        uint32_t aaddr = sA_b +
            (((mbase + (lane & 15)) * SA_STRIDE + ks * 16 + ((lane >> 4) << 3)) << 1);
        ldsm_x4(a0, a1, a2, a3, aaddr);
#pragma unroll
        for (int nt = 0; nt < 16; nt++) {
            uint32_t b0, b1;
            uint32_t baddr = sWa_b + (((ks * 16 + (lane & 15)) * 136 + nt * 8) << 1);
            ldsm_x2t(b0, b1, baddr);
            mma16816(c[nt], a0, a1, a2, a3, b0, b1);
        }
    }
    {
        int r0 = lane >> 2;
#pragma unroll
        for (int nt = 0; nt < 16; nt++) {
            int col0 = nt * 8 + (lane & 3) * 2;
            float u00 = gelu(c[nt][0] + sBa[col0]);
            float u01 = gelu(c[nt][1] + sBa[col0 + 1]);
            float u10 = gelu(c[nt][2] + sBa[col0]);
            float u11 = gelu(c[nt][3] + sBa[col0 + 1]);
            *(__half2*)(sU + (mbase + r0) * 136 + col0) =
                __float22half2_rn(make_float2(u00, u01));
            *(__half2*)(sU + (mbase + r0 + 8) * 136 + col0) =
                __float22half2_rn(make_float2(u10, u11));
        }
    }
    __syncwarp();
    uint32_t sU_b = (uint32_t)__cvta_generic_to_shared(sU);

#pragma unroll
    for (int nt = 0; nt < 16; nt++) { c[nt][0] = c[nt][1] = c[nt][2] = c[nt][3] = 0.f; }
#pragma unroll
    for (int ks = 0; ks < 8; ks++) {
        uint32_t a0, a1, a2, a3;
        uint32_t aaddr = sU_b +
            (((mbase + (lane & 15)) * 136 + ks * 16 + ((lane >> 4) << 3)) << 1);
        ldsm_x4(a0, a1, a2, a3, aaddr);
#pragma unroll
        for (int nt = 0; nt < 16; nt++) {
            uint32_t b0, b1;
            uint32_t baddr = sWb_b + (((ks * 16 + (lane & 15)) * 136 + nt * 8) << 1);
            ldsm_x2t(b0, b1, baddr);
            mma16816(c[nt], a0, a1, a2, a3, b0, b1);
        }
    }

    {
        int r0 = lane >> 2;
        float s0 = 0.f, q0 = 0.f, s1 = 0.f, q1 = 0.f;
#pragma unroll
        for (int nt = 0; nt < 16; nt++) {
            int col0 = nt * 8 + (lane & 3) * 2;
            float y00 = c[nt][0] + sBb[col0];
            float y01 = c[nt][1] + sBb[col0 + 1];
            float y10 = c[nt][2] + sBb[col0];
            float y11 = c[nt][3] + sBb[col0 + 1];
            if (GELU_OUT) { y00 = gelu(y00); y01 = gelu(y01); y10 = gelu(y10); y11 = gelu(y11); }
            c[nt][0] = y00; c[nt][1] = y01; c[nt][2] = y10; c[nt][3] = y11;
            s0 += y00 + y01; q0 += y00 * y00 + y01 * y01;
            s1 += y10 + y11; q1 += y10 * y10 + y11 * y11;
        }
#pragma unroll
        for (int o = 1; o <= 2; o <<= 1) {
            s0 += __shfl_xor_sync(~0u, s0, o); q0 += __shfl_xor_sync(~0u, q0, o);
            s1 += __shfl_xor_sync(~0u, s1, o); q1 += __shfl_xor_sync(~0u, q1, o);
        }
        float mu0 = s0 * (1.f / 128.f);
        float inv0 = rsqrtf(q0 * (1.f / 128.f) - mu0 * mu0 + LN_EPS);
        float mu1 = s1 * (1.f / 128.f);
        float inv1 = rsqrtf(q1 * (1.f / 128.f) - mu1 * mu1 + LN_EPS);
        int node0 = nbase + mbase + r0;
        int node1 = node0 + 8;
#pragma unroll
        for (int nt = 0; nt < 16; nt++) {
            int col0 = nt * 8 + (lane & 3) * 2;
            float gm0 = sGm[col0], gm1 = sGm[col0 + 1];
            float bt0 = sBt[col0], bt1 = sBt[col0 + 1];
            if (node0 < NN) {
                *(__half2*)(out + (size_t)node0 * 128 + col0) = __float22half2_rn(
                    make_float2((c[nt][0] - mu0) * inv0 * gm0 + bt0,
                                (c[nt][1] - mu0) * inv0 * gm1 + bt1));
            }
            if (node1 < NN) {
                *(__half2*)(out + (size_t)node1 * 128 + col0) = __float22half2_rn(
                    make_float2((c[nt][2] - mu1) * inv1 * gm0 + bt0,
                                (c[nt][3] - mu1) * inv1 * gm1 + bt1));
            }
        }
    }
}

// ---------------- APPNP step: 2 rows/warp, 16 lanes x 8 cols, unroll 4 ----------------
template <int FINAL>
__global__ void __launch_bounds__(256) k_appnp16(const __half* __restrict__ cur,
                                                 __half* __restrict__ nxt,
                                                 float* __restrict__ outp,
                                                 const __half* __restrict__ x0h) {
    int gwarp = (blockIdx.x * blockDim.x + threadIdx.x) >> 5;
    int lane = threadIdx.x & 31;
    int row = gwarp * 2 + (lane >> 4);
    if (row >= NN) return;
    int li = lane & 15, c = li * 8;
    int beg = g_rowstart[row], end = g_rowstart[row + 1];
    float2 acc[4] = {{0.f, 0.f}, {0.f, 0.f}, {0.f, 0.f}, {0.f, 0.f}};
    int p = beg;
    for (; p + 4 <= end; p += 4) {
        float2 r0 = g_esw[p];
        float2 r1 = g_esw[p + 1];
        float2 r2 = g_esw[p + 2];
        float2 r3 = g_esw[p + 3];
        uint4 v0 = *(const uint4*)(cur + (size_t)__float_as_int(r0.x) * 128 + c);
        uint4 v1 = *(const uint4*)(cur + (size_t)__float_as_int(r1.x) * 128 + c);
        uint4 v2 = *(const uint4*)(cur + (size_t)__float_as_int(r2.x) * 128 + c);
        uint4 v3 = *(const uint4*)(cur + (size_t)__float_as_int(r3.x) * 128 + c);
        fma8(acc, v0, r0.y);
        fma8(acc, v1, r1.y);
        fma8(acc, v2, r2.y);
        fma8(acc, v3, r3.y);
    }
    for (; p < end; p++) {
        float2 r = g_esw[p];
        uint4 v = *(const uint4*)(cur + (size_t)__float_as_int(r.x) * 128 + c);
        fma8(acc, v, r.y);
    }
    float sw = g_selfw[row];
    uint4 hd = *(const uint4*)(cur + (size_t)row * 128 + c);
    uint4 xv = *(const uint4*)(x0h + (size_t)row * 128 + c);
    fma8(acc, hd, sw);
    float2 x0 = __half22float2(*(__half2*)&xv.x);
    float2 x1 = __half22float2(*(__half2*)&xv.y);
    float2 x2 = __half22float2(*(__half2*)&xv.z);
    float2 x3 = __half22float2(*(__half2*)&xv.w);
    float2 o0 = make_float2(0.9f * acc[0].x + 0.1f * x0.x, 0.9f * acc[0].y + 0.1f * x0.y);
    float2 o1 = make_float2(0.9f * acc[1].x + 0.1f * x1.x, 0.9f * acc[1].y + 0.1f * x1.y);
    float2 o2 = make_float2(0.9f * acc[2].x + 0.1f * x2.x, 0.9f * acc[2].y + 0.1f * x2.y);
    float2 o3 = make_float2(0.9f * acc[3].x + 0.1f * x3.x, 0.9f * acc[3].y + 0.1f * x3.y);
    if (FINAL) {
        float* op = outp + (size_t)row * 128 + c;
        *(float4*)op = make_float4(o0.x, o0.y, o1.x, o1.y);
        *(float4*)(op + 4) = make_float4(o2.x, o2.y, o3.x, o3.y);
    } else {
        uint4 o;
        *(__half2*)&o.x = __float22half2_rn(o0);
        *(__half2*)&o.y = __float22half2_rn(o1);
        *(__half2*)&o.z = __float22half2_rn(o2);
        *(__half2*)&o.w = __float22half2_rn(o3);
        *(uint4*)(nxt + (size_t)row * 128 + c) = o;
    }
}

// ---------------- gate MLP + segment max ----------------
__global__ void __launch_bounds__(256) k_gate(const float* __restrict__ h,
                                              const float* __restrict__ Wg1,
                                              const float* __restrict__ bg1,
                                              const float* __restrict__ Wg2,
                                              const float* __restrict__ bg2,
                                              const void* bt) {
    __shared__ float sW[128 * 64];
    __shared__ float sx[4 * 128];
    __shared__ float sred[8];
    __shared__ float sWg2[64];
    int t = threadIdx.x;
    for (int i = t; i < 128 * 64; i += 256) sW[i] = Wg1[i];
    if (t < 64) sWg2[t] = Wg2[t];
    int nd = t >> 6, j = t & 63, lane = t & 31, w2 = (t >> 5) & 1;
    float bj = bg1[j];
    float b2 = bg2[0];
    int is64 = g_is64b;
    __syncthreads();

    int ntiles = (NN + 3) / 4;
    for (int tile = blockIdx.x; tile < ntiles; tile += gridDim.x) {
        int nbase = tile * 4;
        __syncthreads();
        for (int i = t; i < 4 * 128; i += 256) {
            int n = nbase + (i >> 7);
            sx[i] = (n < NN) ? h[(size_t)n * 128 + (i & 127)] : 0.f;
        }
        __syncthreads();
        const float* xr = sx + nd * 128;
        float v = bj;
#pragma unroll 8
        for (int k = 0; k < 128; k++) v += xr[k] * sW[k * 64 + j];
        v = gelu(v) * sWg2[j];
        for (int o = 16; o; o >>= 1) v += __shfl_xor_sync(~0u, v, o);
        if (lane == 0) sred[nd * 2 + w2] = v;
        __syncthreads();
        if (j == 0) {
            int n = nbase + nd;
            if (n < NN) {
                float gate = sred[nd * 2] + sred[nd * 2 + 1] + b2;
                g_gate[n] = gate;
                int b = ldidx(bt, is64, n);
                atomicMaxF(&g_bmax[b], gate);
            }
        }
    }
}

// ---------------- softmax numerator + denom ----------------
__global__ void k_exp(const void* bt) {
    int i = blockIdx.x * blockDim.x + threadIdx.x;
    if (i >= NN) return;
    int b = ldidx(bt, g_is64b, i);
    float e = expf(g_gate[i] - g_bmax[b]);
    g_gate[i] = e;
    atomicAdd(&g_bsum[b], e);
}

// ---------------- weighted pooling (unnormalized), then divide ----------------
#define GCHUNK 512
__global__ void __launch_bounds__(128) k_gagg(const float* __restrict__ h,
                                              float* __restrict__ outg,
                                              const void* bt) {
    int j = threadIdx.x;
    int base = blockIdx.x * GCHUNK;
    int lim = base + GCHUNK;
    if (lim > NN) lim = NN;
    int is64 = g_is64b;
    float acc = 0.f;
    int curb = -1;
    for (int n = base; n < lim; n++) {
        int b = ldidx(bt, is64, n);
        if (b != curb) {
            if (curb >= 0) atomicAdd(&outg[curb * 128 + j], acc);
            curb = b;
            acc = 0.f;
        }
        acc += g_gate[n] * h[(size_t)n * 128 + j];
    }
    if (curb >= 0) atomicAdd(&outg[curb * 128 + j], acc);
}

__global__ void k_gdiv(float* __restrict__ outg) {
    int i = blockIdx.x * blockDim.x + threadIdx.x;
    if (i >= BB * 128) return;
    float s = g_bsum[i >> 7];
    if (s > 0.f) outg[i] /= s;
}

// ---------------- launch ----------------
extern "C" void kernel_launch(void* const* d_in, const int* in_sizes, int n_in,
                              void* d_out, int out_size) {
    const float* x = (const float*)d_in[0];
    const void* ei = d_in[1];
    const void* bt = d_in[2];
    const float* ea = (const float*)d_in[3];
    const float* We1 = (const float*)d_in[4];  const float* be1 = (const float*)d_in[5];
    const float* W1a = (const float*)d_in[6];  const float* b1a = (const float*)d_in[7];
    const float* W1b = (const float*)d_in[8];  const float* b1b = (const float*)d_in[9];
    const float* g1  = (const float*)d_in[10]; const float* bn1 = (const float*)d_in[11];
    const float* We2 = (const float*)d_in[12]; const float* be2 = (const float*)d_in[13];
    const float* W2a = (const float*)d_in[14]; const float* b2a = (const float*)d_in[15];
    const float* W2b = (const float*)d_in[16]; const float* b2b = (const float*)d_in[17];
    const float* g2  = (const float*)d_in[18]; const float* bn2 = (const float*)d_in[19];
    const float* Wg1 = (const float*)d_in[20]; const float* bg1 = (const float*)d_in[21];
    const float* Wg2 = (const float*)d_in[22]; const float* bg2 = (const float*)d_in[23];

    float* outh = (float*)d_out;
    float* outg = outh + (size_t)NN * 128;

    __half *pT0h, *pHBh, *pA16, *pB16, *pX0h, *pW1ah, *pW1bh, *pW2ah, *pW2bh;
    cudaGetSymbolAddress((void**)&pT0h, g_t0h);
    cudaGetSymbolAddress((void**)&pHBh, g_hBh);
    cudaGetSymbolAddress((void**)&pA16, g_h16A);
    cudaGetSymbolAddress((void**)&pB16, g_h16B);
    cudaGetSymbolAddress((void**)&pX0h, g_x0h);
    cudaGetSymbolAddress((void**)&pW1ah, g_w1ah);
    cudaGetSymbolAddress((void**)&pW1bh, g_w1bh);
    cudaGetSymbolAddress((void**)&pW2ah, g_w2ah);
    cudaGetSymbolAddress((void**)&pW2bh, g_w2bh);

    size_t sz1 = (size_t)(64 * 136 + 128 * 136 + 128 * 72 + 128 * 136) * 2 + 4 * 128 * 4;
    size_t sz2 = (size_t)(128 * 136 + 128 * 136 + 128 * 136 + 128 * 136) * 2 + 4 * 128 * 4;
    cudaFuncSetAttribute(k_mlp_mma<64, 1>, cudaFuncAttributeMaxDynamicSharedMemorySize, (int)sz1);
    cudaFuncSetAttribute(k_mlp_mma<128, 0>, cudaFuncAttributeMaxDynamicSharedMemorySize, (int)sz2);

    k_detect<<<1, 256>>>((const unsigned*)ei, (const unsigned*)bt);
    k_init<<<(NN * 32 + 255) / 256, 256>>>(outg, x);
    k_cvtw<<<64, 256>>>(W1a, W1b, W2a, W2b);
    k_hist<<<(EE + 255) / 256, 256>>>(ei);
    k_scan_sum<<<SNB, 256>>>();
    k_scan_part<<<1, 32>>>();
    k_scan_write<<<SNB, 1024>>>();
    k_build<<<(EE + 255) / 256, 256>>>(ei, ea);

    int ntile = (NN + 127) / 128;
    int pair_blocks = ((NN + 1) / 2 * 32 + 255) / 256;
    k_conv1<<<(NN * 32 + 255) / 256, 256>>>(x, We1, be1);
    k_mlp_mma<64, 1><<<ntile, 256, sz1>>>(pT0h, pA16, pW1ah, b1a, pW1bh, b1b, g1, bn1);
    k_conv2<<<pair_blocks, 256>>>(pA16, pHBh, We2, be2);
    k_mlp_mma<128, 0><<<ntile, 256, sz2>>>(pHBh, pX0h, pW2ah, b2a, pW2bh, b2b, g2, bn2);

    const __half* cur = pX0h;
    for (int it = 0; it < 15; it++) {
        __half* nxt = (it & 1) ? pB16 : pA16;
        k_appnp16<0><<<pair_blocks, 256>>>(cur, nxt, nullptr, pX0h);
        cur = nxt;
    }
    k_appnp16<1><<<pair_blocks, 256>>>(cur, nullptr, outh, pX0h);

    k_gate<<<296, 256>>>(outh, Wg1, bg1, Wg2, bg2, bt);
    k_exp<<<(NN + 255) / 256, 256>>>(bt);
    k_gagg<<<(NN + GCHUNK - 1) / GCHUNK, 128>>>(outh, outg, bt);
    k_gdiv<<<(BB * 128 + 255) / 256, 256>>>(outg);
}